// round 7
// baseline (speedup 1.0000x reference)
#include <cuda_runtime.h>
#include <cuda_bf16.h>
#include <math.h>
#include <stdint.h>

// Problem constants
#define BB   2
#define LL   2048
#define DD   1024
#define HH   16
#define KVH  4
#define HDIM 64
#define BL   (BB * LL)    // 4096

typedef unsigned long long ull;

// ---------------------------------------------------------------------------
// mma.sync / ldmatrix / cp.async helpers (baseline PTX ISA)
// ---------------------------------------------------------------------------
__device__ __forceinline__ uint32_t smem_u32(const void* p) {
    uint32_t a;
    asm("{ .reg .u64 t; cvta.to.shared.u64 t, %1; cvt.u32.u64 %0, t; }"
        : "=r"(a) : "l"(p));
    return a;
}
__device__ __forceinline__ void ldsm4(uint32_t addr, uint32_t* r) {
    asm volatile("ldmatrix.sync.aligned.m8n8.x4.shared.b16 {%0,%1,%2,%3}, [%4];"
                 : "=r"(r[0]), "=r"(r[1]), "=r"(r[2]), "=r"(r[3]) : "r"(addr));
}
__device__ __forceinline__ void ldsm4t(uint32_t addr, uint32_t* r) {
    asm volatile("ldmatrix.sync.aligned.m8n8.x4.trans.shared.b16 {%0,%1,%2,%3}, [%4];"
                 : "=r"(r[0]), "=r"(r[1]), "=r"(r[2]), "=r"(r[3]) : "r"(addr));
}
__device__ __forceinline__ void mma16816(float* d, const uint32_t* a,
                                         const uint32_t* b) {
    asm volatile(
        "mma.sync.aligned.m16n8k16.row.col.f32.bf16.bf16.f32 "
        "{%0,%1,%2,%3}, {%4,%5,%6,%7}, {%8,%9}, {%0,%1,%2,%3};"
        : "+f"(d[0]), "+f"(d[1]), "+f"(d[2]), "+f"(d[3])
        : "r"(a[0]), "r"(a[1]), "r"(a[2]), "r"(a[3]), "r"(b[0]), "r"(b[1]));
}
__device__ __forceinline__ void cp16(uint32_t dst, const void* src) {
    asm volatile("cp.async.cg.shared.global [%0], [%1], 16;"
                 :: "r"(dst), "l"(src) : "memory");
}
#define CP_COMMIT() asm volatile("cp.async.commit_group;" ::: "memory")
#define CP_WAIT1()  asm volatile("cp.async.wait_group 1;" ::: "memory")

__device__ __forceinline__ uint32_t packbf(float lo, float hi) {
    __nv_bfloat162 t = __floats2bfloat162_rn(lo, hi);
    return *(uint32_t*)&t;
}
__device__ __forceinline__ float bfhi(float v) {
    return __bfloat162float(__float2bfloat16(v));
}

// ---------------------------------------------------------------------------
// Scratch (__device__ globals — no allocations allowed)
// ---------------------------------------------------------------------------
__device__ float g_q[BL * HH * HDIM];
__device__ float g_kv[BL * 512];
__device__ float g_ctx[BL * HH * HDIM];

__device__ __nv_bfloat16 g_xhi[BL * DD];
__device__ __nv_bfloat16 g_xlo[BL * DD];
__device__ __nv_bfloat16 g_ctxhi[BL * DD];
__device__ __nv_bfloat16 g_ctxlo[BL * DD];
__device__ __nv_bfloat16 g_wqt_h[DD * DD];
__device__ __nv_bfloat16 g_wqt_l[DD * DD];
__device__ __nv_bfloat16 g_wkvt_h[512 * DD];
__device__ __nv_bfloat16 g_wkvt_l[512 * DD];
__device__ __nv_bfloat16 g_wot_h[DD * DD];
__device__ __nv_bfloat16 g_wot_l[DD * DD];

__device__ __nv_bfloat16 g_qh[BL * DD];
__device__ __nv_bfloat16 g_ql[BL * DD];
__device__ __nv_bfloat16 g_kh[BL * 256];
__device__ __nv_bfloat16 g_kl[BL * 256];
__device__ __nv_bfloat16 g_vh[BL * 256];
__device__ __nv_bfloat16 g_vl[BL * 256];

// ---------------------------------------------------------------------------
// fp32 -> bf16 hi/lo split
// ---------------------------------------------------------------------------
__global__ __launch_bounds__(256)
void cvt_split(const float* __restrict__ in, __nv_bfloat16* __restrict__ hi,
               __nv_bfloat16* __restrict__ lo, int n4) {
    int i = blockIdx.x * 256 + threadIdx.x;
    if (i >= n4) return;
    float4 v = ((const float4*)in)[i];
    float vv[4] = {v.x, v.y, v.z, v.w};
    __nv_bfloat16 h[4], l[4];
#pragma unroll
    for (int j = 0; j < 4; j++) {
        h[j] = __float2bfloat16(vv[j]);
        l[j] = __float2bfloat16(vv[j] - __bfloat162float(h[j]));
    }
    ((uint64_t*)hi)[i] = *(uint64_t*)h;
    ((uint64_t*)lo)[i] = *(uint64_t*)l;
}

// ---------------------------------------------------------------------------
// W [K,N] fp32 -> W^T hi/lo bf16 [N,K]
// ---------------------------------------------------------------------------
__global__ __launch_bounds__(256)
void cvt_transpose(const float* __restrict__ W, __nv_bfloat16* __restrict__ hiT,
                   __nv_bfloat16* __restrict__ loT, int Kd, int Nd) {
    __shared__ float t[32][33];
    int n0 = blockIdx.x << 5, k0 = blockIdx.y << 5;
    int tx = threadIdx.x & 31, ty = threadIdx.x >> 5;
    for (int r = ty; r < 32; r += 8)
        t[r][tx] = W[(size_t)(k0 + r) * Nd + n0 + tx];
    __syncthreads();
    for (int r = ty; r < 32; r += 8) {
        float v = t[tx][r];
        __nv_bfloat16 h = __float2bfloat16(v);
        size_t o = (size_t)(n0 + r) * Kd + k0 + tx;
        hiT[o] = h;
        loT[o] = __float2bfloat16(v - __bfloat162float(h));
    }
}

// ---------------------------------------------------------------------------
// Tensor-core GEMM (mma.sync bf16x3): 2-stage cp.async pipeline, occ 2.
// ---------------------------------------------------------------------------
#define STG_BYTES 40960
#define SUB_BYTES 10240

__global__ __launch_bounds__(256, 2)
void gemm_mma(const __nv_bfloat16* __restrict__ Ahi,
              const __nv_bfloat16* __restrict__ Alo,
              const __nv_bfloat16* __restrict__ Bhi,
              const __nv_bfloat16* __restrict__ Blo,
              float* __restrict__ C, int K, int ldc) {
    extern __shared__ char sm[];
    const uint32_t smb = smem_u32(sm);

    const int tid = threadIdx.x;
    const int lid = tid & 31;
    const int wid = tid >> 5;
    const int wm  = wid >> 1;
    const int wn  = wid & 1;
    const int row0 = blockIdx.y << 7;
    const int col0 = blockIdx.x << 7;
    const int NCH = K >> 5;

    const __nv_bfloat16* srcbase[4] = {Ahi, Alo, Bhi, Blo};

    auto prefetch = [&](int c, int stage) {
#pragma unroll
        for (int it = 0; it < 8; it++) {
            int i = tid + (it << 8);
            int s = i >> 9;
            int j = i & 511;
            int r = j >> 2;
            int u = j & 3;
            int grow = (s < 2 ? row0 : col0) + r;
            const __nv_bfloat16* src =
                srcbase[s] + (size_t)grow * K + (c << 5) + (u << 3);
            uint32_t dst = smb + stage * STG_BYTES + s * SUB_BYTES
                         + r * 80 + (u << 4);
            cp16(dst, src);
        }
    };

    prefetch(0, 0); CP_COMMIT();
    prefetch(1, 1); CP_COMMIT();

    float acc[2][8][4];
#pragma unroll
    for (int a = 0; a < 2; a++)
#pragma unroll
        for (int b = 0; b < 8; b++)
#pragma unroll
            for (int d = 0; d < 4; d++) acc[a][b][d] = 0.0f;

    const uint32_t aoff = (uint32_t)((wm * 32 + (lid & 15)) * 80
                                     + ((lid >> 4) << 4));
    const uint32_t boff = (uint32_t)((wn * 64 + ((lid >> 4) << 3) + (lid & 7)) * 80
                                     + (((lid >> 3) & 1) << 4));

    for (int c = 0; c < NCH; c++) {
        CP_WAIT1();
        __syncthreads();

        const uint32_t sb = smb + (c & 1) * STG_BYTES;
        const uint32_t sa_h = sb;
        const uint32_t sa_l = sb + SUB_BYTES;
        const uint32_t sb_h = sb + 2 * SUB_BYTES;
        const uint32_t sb_l = sb + 3 * SUB_BYTES;

#pragma unroll
        for (int ks = 0; ks < 2; ks++) {
            uint32_t Ah[2][4], Al[2][4];
            ldsm4(sa_h + aoff + ks * 32, Ah[0]);
            ldsm4(sa_h + aoff + 16 * 80 + ks * 32, Ah[1]);
            ldsm4(sa_l + aoff + ks * 32, Al[0]);
            ldsm4(sa_l + aoff + 16 * 80 + ks * 32, Al[1]);
#pragma unroll
            for (int g = 0; g < 4; g++) {
                uint32_t Bh[4], Bl[4];
                ldsm4(sb_h + boff + g * (16 * 80) + ks * 32, Bh);
                ldsm4(sb_l + boff + g * (16 * 80) + ks * 32, Bl);
#pragma unroll
                for (int mi = 0; mi < 2; mi++) {
                    mma16816(acc[mi][2 * g],     Ah[mi], Bh);
                    mma16816(acc[mi][2 * g],     Ah[mi], Bl);
                    mma16816(acc[mi][2 * g],     Al[mi], Bh);
                    mma16816(acc[mi][2 * g + 1], Ah[mi], Bh + 2);
                    mma16816(acc[mi][2 * g + 1], Ah[mi], Bl + 2);
                    mma16816(acc[mi][2 * g + 1], Al[mi], Bh + 2);
                }
            }
        }
        __syncthreads();
        if (c + 2 < NCH) prefetch(c + 2, c & 1);
        CP_COMMIT();
    }

#pragma unroll
    for (int mi = 0; mi < 2; mi++) {
        int r0 = row0 + wm * 32 + mi * 16 + (lid >> 2);
#pragma unroll
        for (int ni = 0; ni < 8; ni++) {
            int cc = col0 + wn * 64 + ni * 8 + ((lid & 3) << 1);
            float2 v0; v0.x = acc[mi][ni][0]; v0.y = acc[mi][ni][1];
            float2 v1; v1.x = acc[mi][ni][2]; v1.y = acc[mi][ni][3];
            *(float2*)(C + (size_t)r0 * ldc + cc)       = v0;
            *(float2*)(C + (size_t)(r0 + 8) * ldc + cc) = v1;
        }
    }
}

// ---------------------------------------------------------------------------
// RoPE + hi/lo split
// ---------------------------------------------------------------------------
__global__ __launch_bounds__(256)
void rope_split(const float* __restrict__ q, const float* __restrict__ kv,
                __nv_bfloat16* __restrict__ qh, __nv_bfloat16* __restrict__ ql,
                __nv_bfloat16* __restrict__ kh, __nv_bfloat16* __restrict__ kl,
                __nv_bfloat16* __restrict__ vh, __nv_bfloat16* __restrict__ vl) {
    const int TQ = BL * HH * 32;
    const int TK = BL * KVH * 32;
    const int TV = BL * KVH * 32;
    int idx = blockIdx.x * 256 + threadIdx.x;
    if (idx < TQ + TK) {
        const float* base;
        size_t o;
        __nv_bfloat16 *dh, *dl;
        int j, pos;
        if (idx < TQ) {
            j = idx & 31;
            int t = idx >> 5;
            int token = t >> 4, h = t & 15;
            pos = token & (LL - 1);
            base = q + ((size_t)t << 6);
            o = (size_t)token * 1024 + h * 64 + j;
            dh = qh; dl = ql;
        } else {
            int id2 = idx - TQ;
            j = id2 & 31;
            int t = id2 >> 5;
            int token = t >> 2, kvh2 = t & 3;
            pos = token & (LL - 1);
            base = kv + (size_t)token * 512 + kvh2 * 64;
            o = (size_t)token * 256 + kvh2 * 64 + j;
            dh = kh; dl = kl;
        }
        float inv = powf(10000.0f, -(float)j * (1.0f / 32.0f));
        float ang = (float)pos * inv;
        float s, c;
        sincosf(ang, &s, &c);
        float x1 = base[j], x2 = base[j + 32];
        float y1 = x1 * c - x2 * s;
        float y2 = x2 * c + x1 * s;
        __nv_bfloat16 h1 = __float2bfloat16(y1);
        __nv_bfloat16 h2 = __float2bfloat16(y2);
        dh[o]      = h1;
        dh[o + 32] = h2;
        dl[o]      = __float2bfloat16(y1 - __bfloat162float(h1));
        dl[o + 32] = __float2bfloat16(y2 - __bfloat162float(h2));
    } else if (idx < TQ + TK + TV) {
        int id2 = idx - TQ - TK;
        int j = id2 & 31;
        int t = id2 >> 5;
        int token = t >> 2, kvh2 = t & 3;
        const float* base = kv + (size_t)token * 512 + 256 + kvh2 * 64;
        size_t o = (size_t)token * 256 + kvh2 * 64 + j;
        float x1 = base[j], x2 = base[j + 32];
        __nv_bfloat16 h1 = __float2bfloat16(x1);
        __nv_bfloat16 h2 = __float2bfloat16(x2);
        vh[o]      = h1;
        vh[o + 32] = h2;
        vl[o]      = __float2bfloat16(x1 - __bfloat162float(h1));
        vl[o + 32] = __float2bfloat16(x2 - __bfloat162float(h2));
    }
}

// ---------------------------------------------------------------------------
// Tensor-core flash attention v3: 256 q-rows/CTA, 8 warps x 32 rows.
// Q lives in a dedicated smem region; Q fragments are re-ldsm'd per k16
// step instead of persisting in registers (kills register spills).
// grid (8, 16, 2), 256 thr, 147.5KB smem, 2-stage KV cp.async pipeline.
// ---------------------------------------------------------------------------
#define AST 144
#define QSUB  (256 * AST)          // 36864 (one Q subtile: 256 rows)
#define KVSUB (64 * AST)           // 9216
#define KVSTG (4 * KVSUB)          // 36864
#define KV_OFF (2 * QSUB)          // 73728
#define ATT_SMEM (KV_OFF + 2 * KVSTG)   // 147456

__global__ __launch_bounds__(256, 1)
void attn_mma(const __nv_bfloat16* __restrict__ qh, const __nv_bfloat16* __restrict__ ql,
              const __nv_bfloat16* __restrict__ kh, const __nv_bfloat16* __restrict__ kl,
              const __nv_bfloat16* __restrict__ vh, const __nv_bfloat16* __restrict__ vl,
              float* __restrict__ ctx) {
    extern __shared__ char sm[];
    const uint32_t smb = smem_u32(sm);

    const int tid = threadIdx.x;
    const int lid = tid & 31;
    const int wid = tid >> 5;
    const int q0  = blockIdx.x << 8;
    const int h   = blockIdx.y;
    const int b   = blockIdx.z;
    const int kvh2 = h >> 2;

    const float slope = exp2f(-0.5f * (float)(h + 1));
    const float scale = 0.125f;

    // ---- stage Q into its permanent smem region (hi @0, lo @QSUB) ----
#pragma unroll
    for (int t = 0; t < 16; t++) {
        int i = tid + (t << 8);
        int s = i >> 11;
        int j = i & 2047;
        int r = j >> 3;
        int u = j & 7;
        const __nv_bfloat16* src =
            (s ? ql : qh) + (size_t)(b * LL + q0 + r) * 1024 + h * 64 + (u << 3);
        cp16(smb + s * QSUB + r * AST + (u << 4), src);
    }
    CP_COMMIT();

    // ---- KV pipeline ----
    const __nv_bfloat16* kvsrc[4] = {kh, kl, vh, vl};
    auto pf = [&](int c, int st) {
#pragma unroll
        for (int t = 0; t < 8; t++) {
            int i = tid + (t << 8);
            int s = i >> 9;
            int j = i & 511;
            int r = j >> 3;
            int u = j & 7;
            const __nv_bfloat16* src =
                kvsrc[s] + (size_t)(b * LL + (c << 6) + r) * 256 + kvh2 * 64 + (u << 3);
            cp16(smb + KV_OFF + st * KVSTG + s * KVSUB + r * AST + (u << 4), src);
        }
    };
    pf(0, 0); CP_COMMIT();
    pf(1, 1); CP_COMMIT();

    // per-thread ldmatrix sub-addresses
    const uint32_t qa0 = (uint32_t)((wid * 32 + (lid & 15)) * AST
                                    + ((lid >> 4) << 4));
    const uint32_t qa1 = qa0 + 16 * AST;
    const uint32_t kaddr = (uint32_t)((((lid >> 4) << 3) + (lid & 7)) * AST
                                      + (((lid >> 3) & 1) << 4));
    const uint32_t vaddr = (uint32_t)((lid & 15) * AST + ((lid >> 4) << 4));

    float o[2][8][4];
    float m[2][2], lsum[2][2];
#pragma unroll
    for (int bl = 0; bl < 2; bl++) {
#pragma unroll
        for (int i = 0; i < 8; i++)
#pragma unroll
            for (int e = 0; e < 4; e++) o[bl][i][e] = 0.0f;
        m[bl][0] = -1e30f; m[bl][1] = -1e30f;
        lsum[bl][0] = 0.0f; lsum[bl][1] = 0.0f;
    }

    const int NTILES = LL / 64;   // 32

    for (int c = 0; c < NTILES; c++) {
        CP_WAIT1();          // Q group + current KV group complete
        __syncthreads();

        const uint32_t sb  = smb + KV_OFF + (c & 1) * KVSTG;
        const uint32_t skh = sb;
        const uint32_t skl = sb + KVSUB;
        const uint32_t svh = sb + 2 * KVSUB;
        const uint32_t svl = sb + 3 * KVSUB;

        // ---- S = Q.K^T for both blocks; Q frags reloaded per ks ----
        float S[2][8][4];
#pragma unroll
        for (int bl = 0; bl < 2; bl++)
#pragma unroll
            for (int i = 0; i < 8; i++)
#pragma unroll
                for (int e = 0; e < 4; e++) S[bl][i][e] = 0.0f;

#pragma unroll
        for (int ks = 0; ks < 4; ks++) {
            uint32_t Q0h[4], Q0l[4], Q1h[4], Q1l[4];
            ldsm4(smb + qa0 + (ks << 5), Q0h);
            ldsm4(smb + QSUB + qa0 + (ks << 5), Q0l);
            ldsm4(smb + qa1 + (ks << 5), Q1h);
            ldsm4(smb + QSUB + qa1 + (ks << 5), Q1l);
#pragma unroll
            for (int g = 0; g < 4; g++) {
                uint32_t Bh[4], Bl[4];
                uint32_t base = (g << 4) * AST + kaddr + (ks << 5);
                ldsm4(skh + base, Bh);
                ldsm4(skl + base, Bl);
                mma16816(S[0][2 * g],     Q0h, Bh);
                mma16816(S[0][2 * g],     Q0h, Bl);
                mma16816(S[0][2 * g],     Q0l, Bh);
                mma16816(S[0][2 * g + 1], Q0h, Bh + 2);
                mma16816(S[0][2 * g + 1], Q0h, Bl + 2);
                mma16816(S[0][2 * g + 1], Q0l, Bh + 2);
                mma16816(S[1][2 * g],     Q1h, Bh);
                mma16816(S[1][2 * g],     Q1h, Bl);
                mma16816(S[1][2 * g],     Q1l, Bh);
                mma16816(S[1][2 * g + 1], Q1h, Bh + 2);
                mma16816(S[1][2 * g + 1], Q1h, Bl + 2);
                mma16816(S[1][2 * g + 1], Q1l, Bh + 2);
            }
        }

        // ---- softmax per block, P -> A-fragments ----
        uint32_t PAh[2][4][4], PAl[2][4][4];
        const float colb = (float)((c << 6) + 2 * (lid & 3));
#pragma unroll
        for (int bl = 0; bl < 2; bl++) {
            const float qrow0 = (float)(q0 + wid * 32 + bl * 16 + (lid >> 2));
            const float qrow1 = qrow0 + 8.0f;
            const float sb0 = slope * (colb - qrow0);
            const float sb1 = slope * (colb - qrow1);
            float mx0 = -1e30f, mx1 = -1e30f;
#pragma unroll
            for (int nt = 0; nt < 8; nt++) {
                float bo = slope * (float)(nt << 3);
                S[bl][nt][0] = fmaf(S[bl][nt][0], scale, sb0 + bo);
                S[bl][nt][1] = fmaf(S[bl][nt][1], scale, sb0 + bo + slope);
                S[bl][nt][2] = fmaf(S[bl][nt][2], scale, sb1 + bo);
                S[bl][nt][3] = fmaf(S[bl][nt][3], scale, sb1 + bo + slope);
                mx0 = fmaxf(mx0, fmaxf(S[bl][nt][0], S[bl][nt][1]));
                mx1 = fmaxf(mx1, fmaxf(S[bl][nt][2], S[bl][nt][3]));
            }
            mx0 = fmaxf(mx0, __shfl_xor_sync(0xffffffffu, mx0, 1));
            mx0 = fmaxf(mx0, __shfl_xor_sync(0xffffffffu, mx0, 2));
            mx1 = fmaxf(mx1, __shfl_xor_sync(0xffffffffu, mx1, 1));
            mx1 = fmaxf(mx1, __shfl_xor_sync(0xffffffffu, mx1, 2));

            float mn0 = fmaxf(m[bl][0], mx0);
            float mn1 = fmaxf(m[bl][1], mx1);
            float corr0 = __expf(m[bl][0] - mn0);
            float corr1 = __expf(m[bl][1] - mn1);
            m[bl][0] = mn0; m[bl][1] = mn1;

            float ps0 = 0.0f, ps1 = 0.0f;
#pragma unroll
            for (int nt = 0; nt < 8; nt++) {
                S[bl][nt][0] = __expf(S[bl][nt][0] - mn0);
                S[bl][nt][1] = __expf(S[bl][nt][1] - mn0);
                S[bl][nt][2] = __expf(S[bl][nt][2] - mn1);
                S[bl][nt][3] = __expf(S[bl][nt][3] - mn1);
                ps0 += S[bl][nt][0] + S[bl][nt][1];
                ps1 += S[bl][nt][2] + S[bl][nt][3];
            }
            ps0 += __shfl_xor_sync(0xffffffffu, ps0, 1);
            ps0 += __shfl_xor_sync(0xffffffffu, ps0, 2);
            ps1 += __shfl_xor_sync(0xffffffffu, ps1, 1);
            ps1 += __shfl_xor_sync(0xffffffffu, ps1, 2);
            lsum[bl][0] = lsum[bl][0] * corr0 + ps0;
            lsum[bl][1] = lsum[bl][1] * corr1 + ps1;

#pragma unroll
            for (int nt = 0; nt < 8; nt++) {
                o[bl][nt][0] *= corr0;
                o[bl][nt][1] *= corr0;
                o[bl][nt][2] *= corr1;
                o[bl][nt][3] *= corr1;
            }

#pragma unroll
            for (int kt = 0; kt < 4; kt++) {
                float p00 = S[bl][2 * kt][0],     p01 = S[bl][2 * kt][1];
                float p02 = S[bl][2 * kt][2],     p03 = S[bl][2 * kt][3];
                float p10 = S[bl][2 * kt + 1][0], p11 = S[bl][2 * kt + 1][1];
                float p12 = S[bl][2 * kt + 1][2], p13 = S[bl][2 * kt + 1][3];
                float h00 = bfhi(p00), h01 = bfhi(p01), h02 = bfhi(p02), h03 = bfhi(p03);
                float h10 = bfhi(p10), h11 = bfhi(p11), h12 = bfhi(p12), h13 = bfhi(p13);
                PAh[bl][kt][0] = packbf(h00, h01);
                PAh[bl][kt][1] = packbf(h02, h03);
                PAh[bl][kt][2] = packbf(h10, h11);
                PAh[bl][kt][3] = packbf(h12, h13);
                PAl[bl][kt][0] = packbf(p00 - h00, p01 - h01);
                PAl[bl][kt][1] = packbf(p02 - h02, p03 - h03);
                PAl[bl][kt][2] = packbf(p10 - h10, p11 - h11);
                PAl[bl][kt][3] = packbf(p12 - h12, p13 - h13);
            }
        }

        // ---- O += P @ V; V frags loaded once, shared by both blocks ----
#pragma unroll
        for (int dg = 0; dg < 4; dg++) {
#pragma unroll
            for (int kt = 0; kt < 4; kt++) {
                uint32_t Bvh[4], Bvl[4];
                uint32_t base = (kt << 4) * AST + vaddr + (dg << 5);
                ldsm4t(svh + base, Bvh);
                ldsm4t(svl + base, Bvl);
#pragma unroll
                for (int bl = 0; bl < 2; bl++) {
                    mma16816(o[bl][2 * dg],     PAh[bl][kt], Bvh);
                    mma16816(o[bl][2 * dg],     PAh[bl][kt], Bvl);
                    mma16816(o[bl][2 * dg],     PAl[bl][kt], Bvh);
                    mma16816(o[bl][2 * dg + 1], PAh[bl][kt], Bvh + 2);
                    mma16816(o[bl][2 * dg + 1], PAh[bl][kt], Bvl + 2);
                    mma16816(o[bl][2 * dg + 1], PAl[bl][kt], Bvh + 2);
                }
            }
        }

        __syncthreads();
        if (c + 2 < NTILES) pf(c + 2, c & 1);
        CP_COMMIT();
    }

    // ---- epilogue ----
#pragma unroll
    for (int bl = 0; bl < 2; bl++) {
        float inv0 = 1.0f / lsum[bl][0];
        float inv1 = 1.0f / lsum[bl][1];
        const int r0 = b * LL + q0 + wid * 32 + bl * 16 + (lid >> 2);
#pragma unroll
        for (int nt = 0; nt < 8; nt++) {
            int cc = h * 64 + nt * 8 + ((lid & 3) << 1);
            float2 v0; v0.x = o[bl][nt][0] * inv0; v0.y = o[bl][nt][1] * inv0;
            float2 v1; v1.x = o[bl][nt][2] * inv1; v1.y = o[bl][nt][3] * inv1;
            *(float2*)(ctx + (size_t)r0 * 1024 + cc)       = v0;
            *(float2*)(ctx + (size_t)(r0 + 8) * 1024 + cc) = v1;
        }
    }
}

// ---------------------------------------------------------------------------
// kernel_launch
// ---------------------------------------------------------------------------
extern "C" void kernel_launch(void* const* d_in, const int* in_sizes, int n_in,
                              void* d_out, int out_size) {
    const float* x  = (const float*)d_in[0];
    const float* Wq = (const float*)d_in[1];
    const float* Wk = (const float*)d_in[2];
    const float* Wv = (const float*)d_in[3];
    const float* Wo = (const float*)d_in[4];
    float* out = (float*)d_out;

    float *pq, *pkv, *pctx;
    cudaGetSymbolAddress((void**)&pq,   g_q);
    cudaGetSymbolAddress((void**)&pkv,  g_kv);
    cudaGetSymbolAddress((void**)&pctx, g_ctx);

    __nv_bfloat16 *xhi, *xlo, *cthi, *ctlo;
    __nv_bfloat16 *wqh, *wql, *wkvh, *wkvl, *woh, *wol;
    __nv_bfloat16 *aqh, *aql, *akh, *akl, *avh, *avl;
    cudaGetSymbolAddress((void**)&xhi,  g_xhi);
    cudaGetSymbolAddress((void**)&xlo,  g_xlo);
    cudaGetSymbolAddress((void**)&cthi, g_ctxhi);
    cudaGetSymbolAddress((void**)&ctlo, g_ctxlo);
    cudaGetSymbolAddress((void**)&wqh,  g_wqt_h);
    cudaGetSymbolAddress((void**)&wql,  g_wqt_l);
    cudaGetSymbolAddress((void**)&wkvh, g_wkvt_h);
    cudaGetSymbolAddress((void**)&wkvl, g_wkvt_l);
    cudaGetSymbolAddress((void**)&woh,  g_wot_h);
    cudaGetSymbolAddress((void**)&wol,  g_wot_l);
    cudaGetSymbolAddress((void**)&aqh,  g_qh);
    cudaGetSymbolAddress((void**)&aql,  g_ql);
    cudaGetSymbolAddress((void**)&akh,  g_kh);
    cudaGetSymbolAddress((void**)&akl,  g_kl);
    cudaGetSymbolAddress((void**)&avh,  g_vh);
    cudaGetSymbolAddress((void**)&avl,  g_vl);

    const int smem_gemm = 2 * STG_BYTES;
    cudaFuncSetAttribute(gemm_mma, cudaFuncAttributeMaxDynamicSharedMemorySize,
                         smem_gemm);
    cudaFuncSetAttribute(attn_mma, cudaFuncAttributeMaxDynamicSharedMemorySize,
                         ATT_SMEM);

    dim3 blk(256);

    // conversions
    cvt_split<<<(BL * DD / 4 + 255) / 256, blk>>>(x, xhi, xlo, BL * DD / 4);
    cvt_transpose<<<dim3(DD / 32, DD / 32), blk>>>(Wq, wqh, wql, DD, DD);
    cvt_transpose<<<dim3(256 / 32, DD / 32), blk>>>(Wk, wkvh, wkvl, DD, 256);
    cvt_transpose<<<dim3(256 / 32, DD / 32), blk>>>(
        Wv, wkvh + 256 * DD, wkvl + 256 * DD, DD, 256);
    cvt_transpose<<<dim3(DD / 32, DD / 32), blk>>>(Wo, woh, wol, DD, DD);

    // projections (tensor cores)
    gemm_mma<<<dim3(DD / 128, BL / 128), blk, smem_gemm>>>(
        xhi, xlo, wqh, wql, pq, DD, DD);
    gemm_mma<<<dim3(512 / 128, BL / 128), blk, smem_gemm>>>(
        xhi, xlo, wkvh, wkvl, pkv, DD, 512);

    // RoPE + split to bf16 hi/lo
    {
        int total = BL * (HH + 2 * KVH) * 32;
        rope_split<<<(total + 255) / 256, blk>>>(pq, pkv, aqh, aql, akh, akl,
                                                 avh, avl);
    }

    // tensor-core attention (256-row q tiles)
    attn_mma<<<dim3(LL / 256, HH, BB), blk, ATT_SMEM>>>(
        aqh, aql, akh, akl, avh, avl, pctx);

    // output projection
    cvt_split<<<(BL * DD / 4 + 255) / 256, blk>>>(pctx, cthi, ctlo, BL * DD / 4);
    gemm_mma<<<dim3(DD / 128, BL / 128), blk, smem_gemm>>>(
        cthi, ctlo, woh, wol, out, DD, DD);
}

// round 8
// speedup vs baseline: 1.4596x; 1.4596x over previous
#include <cuda_runtime.h>
#include <cuda_bf16.h>
#include <math.h>
#include <stdint.h>

// Problem constants
#define BB   2
#define LL   2048
#define DD   1024
#define HH   16
#define KVH  4
#define HDIM 64
#define BL   (BB * LL)    // 4096

typedef unsigned long long ull;

// ---------------------------------------------------------------------------
// mma.sync / ldmatrix / cp.async helpers (baseline PTX ISA)
// ---------------------------------------------------------------------------
__device__ __forceinline__ uint32_t smem_u32(const void* p) {
    uint32_t a;
    asm("{ .reg .u64 t; cvta.to.shared.u64 t, %1; cvt.u32.u64 %0, t; }"
        : "=r"(a) : "l"(p));
    return a;
}
__device__ __forceinline__ void ldsm4(uint32_t addr, uint32_t* r) {
    asm volatile("ldmatrix.sync.aligned.m8n8.x4.shared.b16 {%0,%1,%2,%3}, [%4];"
                 : "=r"(r[0]), "=r"(r[1]), "=r"(r[2]), "=r"(r[3]) : "r"(addr));
}
__device__ __forceinline__ void ldsm4t(uint32_t addr, uint32_t* r) {
    asm volatile("ldmatrix.sync.aligned.m8n8.x4.trans.shared.b16 {%0,%1,%2,%3}, [%4];"
                 : "=r"(r[0]), "=r"(r[1]), "=r"(r[2]), "=r"(r[3]) : "r"(addr));
}
__device__ __forceinline__ void mma16816(float* d, const uint32_t* a,
                                         const uint32_t* b) {
    asm volatile(
        "mma.sync.aligned.m16n8k16.row.col.f32.bf16.bf16.f32 "
        "{%0,%1,%2,%3}, {%4,%5,%6,%7}, {%8,%9}, {%0,%1,%2,%3};"
        : "+f"(d[0]), "+f"(d[1]), "+f"(d[2]), "+f"(d[3])
        : "r"(a[0]), "r"(a[1]), "r"(a[2]), "r"(a[3]), "r"(b[0]), "r"(b[1]));
}
__device__ __forceinline__ void cp16(uint32_t dst, const void* src) {
    asm volatile("cp.async.cg.shared.global [%0], [%1], 16;"
                 :: "r"(dst), "l"(src) : "memory");
}
#define CP_COMMIT() asm volatile("cp.async.commit_group;" ::: "memory")
#define CP_WAIT1()  asm volatile("cp.async.wait_group 1;" ::: "memory")
#define CP_WAIT0()  asm volatile("cp.async.wait_group 0;" ::: "memory")

__device__ __forceinline__ uint32_t packbf(float lo, float hi) {
    __nv_bfloat162 t = __floats2bfloat162_rn(lo, hi);
    return *(uint32_t*)&t;
}
__device__ __forceinline__ float bfhi(float v) {
    return __bfloat162float(__float2bfloat16(v));
}

// ---------------------------------------------------------------------------
// Scratch (__device__ globals — no allocations allowed)
// ---------------------------------------------------------------------------
__device__ float g_q[BL * HH * HDIM];
__device__ float g_kv[BL * 512];
__device__ float g_ctx[BL * HH * HDIM];

__device__ __nv_bfloat16 g_xhi[BL * DD];
__device__ __nv_bfloat16 g_xlo[BL * DD];
__device__ __nv_bfloat16 g_ctxhi[BL * DD];
__device__ __nv_bfloat16 g_ctxlo[BL * DD];
__device__ __nv_bfloat16 g_wqt_h[DD * DD];
__device__ __nv_bfloat16 g_wqt_l[DD * DD];
__device__ __nv_bfloat16 g_wkvt_h[512 * DD];
__device__ __nv_bfloat16 g_wkvt_l[512 * DD];
__device__ __nv_bfloat16 g_wot_h[DD * DD];
__device__ __nv_bfloat16 g_wot_l[DD * DD];

__device__ __nv_bfloat16 g_qh[BL * DD];
__device__ __nv_bfloat16 g_ql[BL * DD];
__device__ __nv_bfloat16 g_kh[BL * 256];
__device__ __nv_bfloat16 g_kl[BL * 256];
__device__ __nv_bfloat16 g_vh[BL * 256];
__device__ __nv_bfloat16 g_vl[BL * 256];

// ---------------------------------------------------------------------------
// fp32 -> bf16 hi/lo split
// ---------------------------------------------------------------------------
__global__ __launch_bounds__(256)
void cvt_split(const float* __restrict__ in, __nv_bfloat16* __restrict__ hi,
               __nv_bfloat16* __restrict__ lo, int n4) {
    int i = blockIdx.x * 256 + threadIdx.x;
    if (i >= n4) return;
    float4 v = ((const float4*)in)[i];
    float vv[4] = {v.x, v.y, v.z, v.w};
    __nv_bfloat16 h[4], l[4];
#pragma unroll
    for (int j = 0; j < 4; j++) {
        h[j] = __float2bfloat16(vv[j]);
        l[j] = __float2bfloat16(vv[j] - __bfloat162float(h[j]));
    }
    ((uint64_t*)hi)[i] = *(uint64_t*)h;
    ((uint64_t*)lo)[i] = *(uint64_t*)l;
}

// ---------------------------------------------------------------------------
// Batched transpose for Wq, Wk, Wv: W [K,N] fp32 -> W^T hi/lo bf16 [N,K]
// z=0: Wq (N=1024) -> wqt; z=1: Wk (N=256) -> wkvt rows 0..255;
// z=2: Wv (N=256) -> wkvt rows 256..511
// ---------------------------------------------------------------------------
__global__ __launch_bounds__(256)
void cvt_transpose3(const float* __restrict__ Wq, const float* __restrict__ Wk,
                    const float* __restrict__ Wv,
                    __nv_bfloat16* __restrict__ wqh, __nv_bfloat16* __restrict__ wql,
                    __nv_bfloat16* __restrict__ wkvh, __nv_bfloat16* __restrict__ wkvl) {
    __shared__ float t[32][33];
    const int z = blockIdx.z;
    const float* W;
    __nv_bfloat16 *hiT, *loT;
    int Nd, rowoff = 0;
    if (z == 0) { W = Wq; hiT = wqh; loT = wql; Nd = 1024; }
    else if (z == 1) { W = Wk; hiT = wkvh; loT = wkvl; Nd = 256; }
    else { W = Wv; hiT = wkvh; loT = wkvl; Nd = 256; rowoff = 256; }
    if (blockIdx.x * 32 >= Nd) return;

    int n0 = blockIdx.x << 5, k0 = blockIdx.y << 5;
    int tx = threadIdx.x & 31, ty = threadIdx.x >> 5;
    for (int r = ty; r < 32; r += 8)
        t[r][tx] = W[(size_t)(k0 + r) * Nd + n0 + tx];
    __syncthreads();
    for (int r = ty; r < 32; r += 8) {
        float v = t[tx][r];
        __nv_bfloat16 h = __float2bfloat16(v);
        size_t o = (size_t)(rowoff + n0 + r) * DD + k0 + tx;
        hiT[o] = h;
        loT[o] = __float2bfloat16(v - __bfloat162float(h));
    }
}

// single transpose (for Wo)
__global__ __launch_bounds__(256)
void cvt_transpose(const float* __restrict__ W, __nv_bfloat16* __restrict__ hiT,
                   __nv_bfloat16* __restrict__ loT, int Kd, int Nd) {
    __shared__ float t[32][33];
    int n0 = blockIdx.x << 5, k0 = blockIdx.y << 5;
    int tx = threadIdx.x & 31, ty = threadIdx.x >> 5;
    for (int r = ty; r < 32; r += 8)
        t[r][tx] = W[(size_t)(k0 + r) * Nd + n0 + tx];
    __syncthreads();
    for (int r = ty; r < 32; r += 8) {
        float v = t[tx][r];
        __nv_bfloat16 h = __float2bfloat16(v);
        size_t o = (size_t)(n0 + r) * Kd + k0 + tx;
        hiT[o] = h;
        loT[o] = __float2bfloat16(v - __bfloat162float(h));
    }
}

// ---------------------------------------------------------------------------
// Tensor-core GEMM (mma.sync bf16x3), 2-stage cp.async, occ 2.
// Supports two output panels in one launch: bx < nx1 -> (B1, C1, ldc1),
// else (B2, C2, ldc2) with col0 rebased.
// ---------------------------------------------------------------------------
#define STG_BYTES 40960
#define SUB_BYTES 10240

__global__ __launch_bounds__(256, 2)
void gemm_mma(const __nv_bfloat16* __restrict__ Ahi,
              const __nv_bfloat16* __restrict__ Alo,
              const __nv_bfloat16* __restrict__ B1h,
              const __nv_bfloat16* __restrict__ B1l,
              float* __restrict__ C1, int ldc1, int nx1,
              const __nv_bfloat16* __restrict__ B2h,
              const __nv_bfloat16* __restrict__ B2l,
              float* __restrict__ C2, int ldc2, int K) {
    extern __shared__ char sm[];
    const uint32_t smb = smem_u32(sm);

    const int tid = threadIdx.x;
    const int lid = tid & 31;
    const int wid = tid >> 5;
    const int wm  = wid >> 1;
    const int wn  = wid & 1;
    const int row0 = blockIdx.y << 7;
    const int NCH = K >> 5;

    const __nv_bfloat16 *Bhi, *Blo;
    float* C;
    int ldc, col0;
    if ((int)blockIdx.x < nx1) {
        Bhi = B1h; Blo = B1l; C = C1; ldc = ldc1; col0 = blockIdx.x << 7;
    } else {
        Bhi = B2h; Blo = B2l; C = C2; ldc = ldc2;
        col0 = ((int)blockIdx.x - nx1) << 7;
    }

    const __nv_bfloat16* srcbase[4] = {Ahi, Alo, Bhi, Blo};

    auto prefetch = [&](int c, int stage) {
#pragma unroll
        for (int it = 0; it < 8; it++) {
            int i = tid + (it << 8);
            int s = i >> 9;
            int j = i & 511;
            int r = j >> 2;
            int u = j & 3;
            int grow = (s < 2 ? row0 : col0) + r;
            const __nv_bfloat16* src =
                srcbase[s] + (size_t)grow * K + (c << 5) + (u << 3);
            uint32_t dst = smb + stage * STG_BYTES + s * SUB_BYTES
                         + r * 80 + (u << 4);
            cp16(dst, src);
        }
    };

    prefetch(0, 0); CP_COMMIT();
    prefetch(1, 1); CP_COMMIT();

    float acc[2][8][4];
#pragma unroll
    for (int a = 0; a < 2; a++)
#pragma unroll
        for (int b = 0; b < 8; b++)
#pragma unroll
            for (int d = 0; d < 4; d++) acc[a][b][d] = 0.0f;

    const uint32_t aoff = (uint32_t)((wm * 32 + (lid & 15)) * 80
                                     + ((lid >> 4) << 4));
    const uint32_t boff = (uint32_t)((wn * 64 + ((lid >> 4) << 3) + (lid & 7)) * 80
                                     + (((lid >> 3) & 1) << 4));

    for (int c = 0; c < NCH; c++) {
        CP_WAIT1();
        __syncthreads();

        const uint32_t sb = smb + (c & 1) * STG_BYTES;
        const uint32_t sa_h = sb;
        const uint32_t sa_l = sb + SUB_BYTES;
        const uint32_t sb_h = sb + 2 * SUB_BYTES;
        const uint32_t sb_l = sb + 3 * SUB_BYTES;

#pragma unroll
        for (int ks = 0; ks < 2; ks++) {
            uint32_t Ah[2][4], Al[2][4];
            ldsm4(sa_h + aoff + ks * 32, Ah[0]);
            ldsm4(sa_h + aoff + 16 * 80 + ks * 32, Ah[1]);
            ldsm4(sa_l + aoff + ks * 32, Al[0]);
            ldsm4(sa_l + aoff + 16 * 80 + ks * 32, Al[1]);
#pragma unroll
            for (int g = 0; g < 4; g++) {
                uint32_t Bh[4], Bl[4];
                ldsm4(sb_h + boff + g * (16 * 80) + ks * 32, Bh);
                ldsm4(sb_l + boff + g * (16 * 80) + ks * 32, Bl);
#pragma unroll
                for (int mi = 0; mi < 2; mi++) {
                    mma16816(acc[mi][2 * g],     Ah[mi], Bh);
                    mma16816(acc[mi][2 * g],     Ah[mi], Bl);
                    mma16816(acc[mi][2 * g],     Al[mi], Bh);
                    mma16816(acc[mi][2 * g + 1], Ah[mi], Bh + 2);
                    mma16816(acc[mi][2 * g + 1], Ah[mi], Bl + 2);
                    mma16816(acc[mi][2 * g + 1], Al[mi], Bh + 2);
                }
            }
        }
        __syncthreads();
        if (c + 2 < NCH) prefetch(c + 2, c & 1);
        CP_COMMIT();
    }

#pragma unroll
    for (int mi = 0; mi < 2; mi++) {
        int r0 = row0 + wm * 32 + mi * 16 + (lid >> 2);
#pragma unroll
        for (int ni = 0; ni < 8; ni++) {
            int cc = col0 + wn * 64 + ni * 8 + ((lid & 3) << 1);
            float2 v0; v0.x = acc[mi][ni][0]; v0.y = acc[mi][ni][1];
            float2 v1; v1.x = acc[mi][ni][2]; v1.y = acc[mi][ni][3];
            *(float2*)(C + (size_t)r0 * ldc + cc)       = v0;
            *(float2*)(C + (size_t)(r0 + 8) * ldc + cc) = v1;
        }
    }
}

// ---------------------------------------------------------------------------
// RoPE + hi/lo split
// ---------------------------------------------------------------------------
__global__ __launch_bounds__(256)
void rope_split(const float* __restrict__ q, const float* __restrict__ kv,
                __nv_bfloat16* __restrict__ qh, __nv_bfloat16* __restrict__ ql,
                __nv_bfloat16* __restrict__ kh, __nv_bfloat16* __restrict__ kl,
                __nv_bfloat16* __restrict__ vh, __nv_bfloat16* __restrict__ vl) {
    const int TQ = BL * HH * 32;
    const int TK = BL * KVH * 32;
    const int TV = BL * KVH * 32;
    int idx = blockIdx.x * 256 + threadIdx.x;
    if (idx < TQ + TK) {
        const float* base;
        size_t o;
        __nv_bfloat16 *dh, *dl;
        int j, pos;
        if (idx < TQ) {
            j = idx & 31;
            int t = idx >> 5;
            int token = t >> 4, h = t & 15;
            pos = token & (LL - 1);
            base = q + ((size_t)t << 6);
            o = (size_t)token * 1024 + h * 64 + j;
            dh = qh; dl = ql;
        } else {
            int id2 = idx - TQ;
            j = id2 & 31;
            int t = id2 >> 5;
            int token = t >> 2, kvh2 = t & 3;
            pos = token & (LL - 1);
            base = kv + (size_t)token * 512 + kvh2 * 64;
            o = (size_t)token * 256 + kvh2 * 64 + j;
            dh = kh; dl = kl;
        }
        float inv = powf(10000.0f, -(float)j * (1.0f / 32.0f));
        float ang = (float)pos * inv;
        float s, c;
        sincosf(ang, &s, &c);
        float x1 = base[j], x2 = base[j + 32];
        float y1 = x1 * c - x2 * s;
        float y2 = x2 * c + x1 * s;
        __nv_bfloat16 h1 = __float2bfloat16(y1);
        __nv_bfloat16 h2 = __float2bfloat16(y2);
        dh[o]      = h1;
        dh[o + 32] = h2;
        dl[o]      = __float2bfloat16(y1 - __bfloat162float(h1));
        dl[o + 32] = __float2bfloat16(y2 - __bfloat162float(h2));
    } else if (idx < TQ + TK + TV) {
        int id2 = idx - TQ - TK;
        int j = id2 & 31;
        int t = id2 >> 5;
        int token = t >> 2, kvh2 = t & 3;
        const float* base = kv + (size_t)token * 512 + 256 + kvh2 * 64;
        size_t o = (size_t)token * 256 + kvh2 * 64 + j;
        float x1 = base[j], x2 = base[j + 32];
        __nv_bfloat16 h1 = __float2bfloat16(x1);
        __nv_bfloat16 h2 = __float2bfloat16(x2);
        vh[o]      = h1;
        vh[o + 32] = h2;
        vl[o]      = __float2bfloat16(x1 - __bfloat162float(h1));
        vl[o + 32] = __float2bfloat16(x2 - __bfloat162float(h2));
    }
}

// ---------------------------------------------------------------------------
// Tensor-core flash attention (round-6 structure, best known):
// 256 q-rows/CTA, 8 warps x 32 rows (two m16 blocks/warp).
// K/V fragments ldsm'd once per tile, shared by both blocks.
// Q staged through KV buffers, fragments persist in registers.
// grid (8, 16, 2), 256 thr, 73.7KB smem, 2-stage KV cp.async pipeline.
// ---------------------------------------------------------------------------
#define AST 144
#define KVSUB (64 * AST)           // 9216
#define KVSTG (4 * KVSUB)          // 36864
#define QSUB  KVSTG                // 36864 = 256 rows * 144B
#define ATT_SMEM (2 * KVSTG)       // 73728

__global__ __launch_bounds__(256, 1)
void attn_mma(const __nv_bfloat16* __restrict__ qh, const __nv_bfloat16* __restrict__ ql,
              const __nv_bfloat16* __restrict__ kh, const __nv_bfloat16* __restrict__ kl,
              const __nv_bfloat16* __restrict__ vh, const __nv_bfloat16* __restrict__ vl,
              float* __restrict__ ctx) {
    extern __shared__ char sm[];
    const uint32_t smb = smem_u32(sm);

    const int tid = threadIdx.x;
    const int lid = tid & 31;
    const int wid = tid >> 5;
    const int q0  = blockIdx.x << 8;
    const int h   = blockIdx.y;
    const int b   = blockIdx.z;
    const int kvh2 = h >> 2;

    const float slope = exp2f(-0.5f * (float)(h + 1));
    const float scale = 0.125f;

    // ---- stage Q (hi at 0, lo at QSUB) through the KV buffer region ----
#pragma unroll
    for (int t = 0; t < 16; t++) {
        int i = tid + (t << 8);
        int s = i >> 11;
        int j = i & 2047;
        int r = j >> 3;
        int u = j & 7;
        const __nv_bfloat16* src =
            (s ? ql : qh) + (size_t)(b * LL + q0 + r) * 1024 + h * 64 + (u << 3);
        cp16(smb + s * QSUB + r * AST + (u << 4), src);
    }
    CP_COMMIT();
    CP_WAIT0();
    __syncthreads();

    // ---- Q fragments for both 16-row blocks -> registers ----
    uint32_t AQh[2][4][4], AQl[2][4][4];
#pragma unroll
    for (int bl = 0; bl < 2; bl++) {
        uint32_t qaddr = (uint32_t)((wid * 32 + bl * 16 + (lid & 15)) * AST
                                    + ((lid >> 4) << 4));
#pragma unroll
        for (int kt = 0; kt < 4; kt++) {
            ldsm4(smb + qaddr + kt * 32, AQh[bl][kt]);
            ldsm4(smb + QSUB + qaddr + kt * 32, AQl[bl][kt]);
        }
    }
    __syncthreads();   // all warps done reading Q before KV overwrites

    // ---- KV pipeline ----
    const __nv_bfloat16* kvsrc[4] = {kh, kl, vh, vl};
    auto pf = [&](int c, int st) {
#pragma unroll
        for (int t = 0; t < 8; t++) {
            int i = tid + (t << 8);
            int s = i >> 9;
            int j = i & 511;
            int r = j >> 3;
            int u = j & 7;
            const __nv_bfloat16* src =
                kvsrc[s] + (size_t)(b * LL + (c << 6) + r) * 256 + kvh2 * 64 + (u << 3);
            cp16(smb + st * KVSTG + s * KVSUB + r * AST + (u << 4), src);
        }
    };
    pf(0, 0); CP_COMMIT();
    pf(1, 1); CP_COMMIT();

    const uint32_t kaddr = (uint32_t)((((lid >> 4) << 3) + (lid & 7)) * AST
                                      + (((lid >> 3) & 1) << 4));
    const uint32_t vaddr = (uint32_t)((lid & 15) * AST + ((lid >> 4) << 4));

    float o[2][8][4];
    float m[2][2], lsum[2][2];
#pragma unroll
    for (int bl = 0; bl < 2; bl++) {
#pragma unroll
        for (int i = 0; i < 8; i++)
#pragma unroll
            for (int e = 0; e < 4; e++) o[bl][i][e] = 0.0f;
        m[bl][0] = -1e30f; m[bl][1] = -1e30f;
        lsum[bl][0] = 0.0f; lsum[bl][1] = 0.0f;
    }

    const int NTILES = LL / 64;   // 32

    for (int c = 0; c < NTILES; c++) {
        CP_WAIT1();
        __syncthreads();

        const uint32_t sb  = smb + (c & 1) * KVSTG;
        const uint32_t skh = sb;
        const uint32_t skl = sb + KVSUB;
        const uint32_t svh = sb + 2 * KVSUB;
        const uint32_t svl = sb + 3 * KVSUB;

        // ---- S = Q.K^T for both blocks; K frags loaded once ----
        float S[2][8][4];
#pragma unroll
        for (int bl = 0; bl < 2; bl++)
#pragma unroll
            for (int i = 0; i < 8; i++)
#pragma unroll
                for (int e = 0; e < 4; e++) S[bl][i][e] = 0.0f;

#pragma unroll
        for (int g = 0; g < 4; g++) {
#pragma unroll
            for (int ks = 0; ks < 4; ks++) {
                uint32_t Bh[4], Bl[4];
                uint32_t base = (g << 4) * AST + kaddr + (ks << 5);
                ldsm4(skh + base, Bh);
                ldsm4(skl + base, Bl);
#pragma unroll
                for (int bl = 0; bl < 2; bl++) {
                    mma16816(S[bl][2 * g],     AQh[bl][ks], Bh);
                    mma16816(S[bl][2 * g],     AQh[bl][ks], Bl);
                    mma16816(S[bl][2 * g],     AQl[bl][ks], Bh);
                    mma16816(S[bl][2 * g + 1], AQh[bl][ks], Bh + 2);
                    mma16816(S[bl][2 * g + 1], AQh[bl][ks], Bl + 2);
                    mma16816(S[bl][2 * g + 1], AQl[bl][ks], Bh + 2);
                }
            }
        }

        // ---- softmax per block, P -> A-fragments ----
        uint32_t PAh[2][4][4], PAl[2][4][4];
        const float colb = (float)((c << 6) + 2 * (lid & 3));
#pragma unroll
        for (int bl = 0; bl < 2; bl++) {
            const float qrow0 = (float)(q0 + wid * 32 + bl * 16 + (lid >> 2));
            const float qrow1 = qrow0 + 8.0f;
            const float sb0 = slope * (colb - qrow0);
            const float sb1 = slope * (colb - qrow1);
            float mx0 = -1e30f, mx1 = -1e30f;
#pragma unroll
            for (int nt = 0; nt < 8; nt++) {
                float bo = slope * (float)(nt << 3);
                S[bl][nt][0] = fmaf(S[bl][nt][0], scale, sb0 + bo);
                S[bl][nt][1] = fmaf(S[bl][nt][1], scale, sb0 + bo + slope);
                S[bl][nt][2] = fmaf(S[bl][nt][2], scale, sb1 + bo);
                S[bl][nt][3] = fmaf(S[bl][nt][3], scale, sb1 + bo + slope);
                mx0 = fmaxf(mx0, fmaxf(S[bl][nt][0], S[bl][nt][1]));
                mx1 = fmaxf(mx1, fmaxf(S[bl][nt][2], S[bl][nt][3]));
            }
            mx0 = fmaxf(mx0, __shfl_xor_sync(0xffffffffu, mx0, 1));
            mx0 = fmaxf(mx0, __shfl_xor_sync(0xffffffffu, mx0, 2));
            mx1 = fmaxf(mx1, __shfl_xor_sync(0xffffffffu, mx1, 1));
            mx1 = fmaxf(mx1, __shfl_xor_sync(0xffffffffu, mx1, 2));

            float mn0 = fmaxf(m[bl][0], mx0);
            float mn1 = fmaxf(m[bl][1], mx1);
            float corr0 = __expf(m[bl][0] - mn0);
            float corr1 = __expf(m[bl][1] - mn1);
            m[bl][0] = mn0; m[bl][1] = mn1;

            float ps0 = 0.0f, ps1 = 0.0f;
#pragma unroll
            for (int nt = 0; nt < 8; nt++) {
                S[bl][nt][0] = __expf(S[bl][nt][0] - mn0);
                S[bl][nt][1] = __expf(S[bl][nt][1] - mn0);
                S[bl][nt][2] = __expf(S[bl][nt][2] - mn1);
                S[bl][nt][3] = __expf(S[bl][nt][3] - mn1);
                ps0 += S[bl][nt][0] + S[bl][nt][1];
                ps1 += S[bl][nt][2] + S[bl][nt][3];
            }
            ps0 += __shfl_xor_sync(0xffffffffu, ps0, 1);
            ps0 += __shfl_xor_sync(0xffffffffu, ps0, 2);
            ps1 += __shfl_xor_sync(0xffffffffu, ps1, 1);
            ps1 += __shfl_xor_sync(0xffffffffu, ps1, 2);
            lsum[bl][0] = lsum[bl][0] * corr0 + ps0;
            lsum[bl][1] = lsum[bl][1] * corr1 + ps1;

#pragma unroll
            for (int nt = 0; nt < 8; nt++) {
                o[bl][nt][0] *= corr0;
                o[bl][nt][1] *= corr0;
                o[bl][nt][2] *= corr1;
                o[bl][nt][3] *= corr1;
            }

#pragma unroll
            for (int kt = 0; kt < 4; kt++) {
                float p00 = S[bl][2 * kt][0],     p01 = S[bl][2 * kt][1];
                float p02 = S[bl][2 * kt][2],     p03 = S[bl][2 * kt][3];
                float p10 = S[bl][2 * kt + 1][0], p11 = S[bl][2 * kt + 1][1];
                float p12 = S[bl][2 * kt + 1][2], p13 = S[bl][2 * kt + 1][3];
                float h00 = bfhi(p00), h01 = bfhi(p01), h02 = bfhi(p02), h03 = bfhi(p03);
                float h10 = bfhi(p10), h11 = bfhi(p11), h12 = bfhi(p12), h13 = bfhi(p13);
                PAh[bl][kt][0] = packbf(h00, h01);
                PAh[bl][kt][1] = packbf(h02, h03);
                PAh[bl][kt][2] = packbf(h10, h11);
                PAh[bl][kt][3] = packbf(h12, h13);
                PAl[bl][kt][0] = packbf(p00 - h00, p01 - h01);
                PAl[bl][kt][1] = packbf(p02 - h02, p03 - h03);
                PAl[bl][kt][2] = packbf(p10 - h10, p11 - h11);
                PAl[bl][kt][3] = packbf(p12 - h12, p13 - h13);
            }
        }

        // ---- O += P @ V; V frags loaded once, shared by both blocks ----
#pragma unroll
        for (int dg = 0; dg < 4; dg++) {
#pragma unroll
            for (int kt = 0; kt < 4; kt++) {
                uint32_t Bvh[4], Bvl[4];
                uint32_t base = (kt << 4) * AST + vaddr + (dg << 5);
                ldsm4t(svh + base, Bvh);
                ldsm4t(svl + base, Bvl);
#pragma unroll
                for (int bl = 0; bl < 2; bl++) {
                    mma16816(o[bl][2 * dg],     PAh[bl][kt], Bvh);
                    mma16816(o[bl][2 * dg],     PAh[bl][kt], Bvl);
                    mma16816(o[bl][2 * dg],     PAl[bl][kt], Bvh);
                    mma16816(o[bl][2 * dg + 1], PAh[bl][kt], Bvh + 2);
                    mma16816(o[bl][2 * dg + 1], PAh[bl][kt], Bvl + 2);
                    mma16816(o[bl][2 * dg + 1], PAl[bl][kt], Bvh + 2);
                }
            }
        }

        __syncthreads();
        if (c + 2 < NTILES) pf(c + 2, c & 1);
        CP_COMMIT();
    }

    // ---- epilogue ----
#pragma unroll
    for (int bl = 0; bl < 2; bl++) {
        float inv0 = 1.0f / lsum[bl][0];
        float inv1 = 1.0f / lsum[bl][1];
        const int r0 = b * LL + q0 + wid * 32 + bl * 16 + (lid >> 2);
#pragma unroll
        for (int nt = 0; nt < 8; nt++) {
            int cc = h * 64 + nt * 8 + ((lid & 3) << 1);
            float2 v0; v0.x = o[bl][nt][0] * inv0; v0.y = o[bl][nt][1] * inv0;
            float2 v1; v1.x = o[bl][nt][2] * inv1; v1.y = o[bl][nt][3] * inv1;
            *(float2*)(ctx + (size_t)r0 * 1024 + cc)       = v0;
            *(float2*)(ctx + (size_t)(r0 + 8) * 1024 + cc) = v1;
        }
    }
}

// ---------------------------------------------------------------------------
// kernel_launch
// Launch order (ncu captures index 5 = attn_mma):
//   0 cvt_split(x)  1 cvt_transpose3  2 cvt_transpose(Wo)
//   3 gemm_mma(Q+KV merged)  4 rope_split  5 attn_mma
//   6 cvt_split(ctx)  7 gemm_mma(O)
// ---------------------------------------------------------------------------
extern "C" void kernel_launch(void* const* d_in, const int* in_sizes, int n_in,
                              void* d_out, int out_size) {
    const float* x  = (const float*)d_in[0];
    const float* Wq = (const float*)d_in[1];
    const float* Wk = (const float*)d_in[2];
    const float* Wv = (const float*)d_in[3];
    const float* Wo = (const float*)d_in[4];
    float* out = (float*)d_out;

    float *pq, *pkv, *pctx;
    cudaGetSymbolAddress((void**)&pq,   g_q);
    cudaGetSymbolAddress((void**)&pkv,  g_kv);
    cudaGetSymbolAddress((void**)&pctx, g_ctx);

    __nv_bfloat16 *xhi, *xlo, *cthi, *ctlo;
    __nv_bfloat16 *wqh, *wql, *wkvh, *wkvl, *woh, *wol;
    __nv_bfloat16 *aqh, *aql, *akh, *akl, *avh, *avl;
    cudaGetSymbolAddress((void**)&xhi,  g_xhi);
    cudaGetSymbolAddress((void**)&xlo,  g_xlo);
    cudaGetSymbolAddress((void**)&cthi, g_ctxhi);
    cudaGetSymbolAddress((void**)&ctlo, g_ctxlo);
    cudaGetSymbolAddress((void**)&wqh,  g_wqt_h);
    cudaGetSymbolAddress((void**)&wql,  g_wqt_l);
    cudaGetSymbolAddress((void**)&wkvh, g_wkvt_h);
    cudaGetSymbolAddress((void**)&wkvl, g_wkvt_l);
    cudaGetSymbolAddress((void**)&woh,  g_wot_h);
    cudaGetSymbolAddress((void**)&wol,  g_wot_l);
    cudaGetSymbolAddress((void**)&aqh,  g_qh);
    cudaGetSymbolAddress((void**)&aql,  g_ql);
    cudaGetSymbolAddress((void**)&akh,  g_kh);
    cudaGetSymbolAddress((void**)&akl,  g_kl);
    cudaGetSymbolAddress((void**)&avh,  g_vh);
    cudaGetSymbolAddress((void**)&avl,  g_vl);

    const int smem_gemm = 2 * STG_BYTES;   // 81920
    cudaFuncSetAttribute(gemm_mma, cudaFuncAttributeMaxDynamicSharedMemorySize,
                         smem_gemm);
    cudaFuncSetAttribute(attn_mma, cudaFuncAttributeMaxDynamicSharedMemorySize,
                         ATT_SMEM);

    dim3 blk(256);

    // 0: x split
    cvt_split<<<(BL * DD / 4 + 255) / 256, blk>>>(x, xhi, xlo, BL * DD / 4);
    // 1: Wq/Wk/Wv transpose+split (batched)
    cvt_transpose3<<<dim3(32, 32, 3), blk>>>(Wq, Wk, Wv, wqh, wql, wkvh, wkvl);
    // 2: Wo transpose+split
    cvt_transpose<<<dim3(32, 32), blk>>>(Wo, woh, wol, DD, DD);

    // 3: Q + KV projections in ONE launch (bx<8 -> Q panel, else KV panel)
    gemm_mma<<<dim3(12, BL / 128), blk, smem_gemm>>>(
        xhi, xlo, wqh, wql, pq, DD, 8, wkvh, wkvl, pkv, 512, DD);

    // 4: RoPE + split to bf16 hi/lo
    {
        int total = BL * (HH + 2 * KVH) * 32;
        rope_split<<<(total + 255) / 256, blk>>>(pq, pkv, aqh, aql, akh, akl,
                                                 avh, avl);
    }

    // 5: tensor-core attention (256-row q tiles)  <-- ncu capture slot
    attn_mma<<<dim3(LL / 256, HH, BB), blk, ATT_SMEM>>>(
        aqh, aql, akh, akl, avh, avl, pctx);

    // 6: ctx split
    cvt_split<<<(BL * DD / 4 + 255) / 256, blk>>>(pctx, cthi, ctlo, BL * DD / 4);
    // 7: output projection
    gemm_mma<<<dim3(8, BL / 128), blk, smem_gemm>>>(
        cthi, ctlo, woh, wol, out, DD, 8,
        (const __nv_bfloat16*)0, (const __nv_bfloat16*)0, (float*)0, 0, DD);
}

// round 9
// speedup vs baseline: 1.4960x; 1.0249x over previous
#include <cuda_runtime.h>
#include <cuda_bf16.h>
#include <math.h>
#include <stdint.h>

// Problem constants
#define BB   2
#define LL   2048
#define DD   1024
#define HH   16
#define KVH  4
#define HDIM 64
#define BL   (BB * LL)    // 4096

typedef unsigned long long ull;

// ---------------------------------------------------------------------------
// mma.sync / ldmatrix / cp.async helpers (baseline PTX ISA)
// ---------------------------------------------------------------------------
__device__ __forceinline__ uint32_t smem_u32(const void* p) {
    uint32_t a;
    asm("{ .reg .u64 t; cvta.to.shared.u64 t, %1; cvt.u32.u64 %0, t; }"
        : "=r"(a) : "l"(p));
    return a;
}
__device__ __forceinline__ void ldsm4(uint32_t addr, uint32_t* r) {
    asm volatile("ldmatrix.sync.aligned.m8n8.x4.shared.b16 {%0,%1,%2,%3}, [%4];"
                 : "=r"(r[0]), "=r"(r[1]), "=r"(r[2]), "=r"(r[3]) : "r"(addr));
}
__device__ __forceinline__ void ldsm4t(uint32_t addr, uint32_t* r) {
    asm volatile("ldmatrix.sync.aligned.m8n8.x4.trans.shared.b16 {%0,%1,%2,%3}, [%4];"
                 : "=r"(r[0]), "=r"(r[1]), "=r"(r[2]), "=r"(r[3]) : "r"(addr));
}
__device__ __forceinline__ void mma16816(float* d, const uint32_t* a,
                                         const uint32_t* b) {
    asm volatile(
        "mma.sync.aligned.m16n8k16.row.col.f32.bf16.bf16.f32 "
        "{%0,%1,%2,%3}, {%4,%5,%6,%7}, {%8,%9}, {%0,%1,%2,%3};"
        : "+f"(d[0]), "+f"(d[1]), "+f"(d[2]), "+f"(d[3])
        : "r"(a[0]), "r"(a[1]), "r"(a[2]), "r"(a[3]), "r"(b[0]), "r"(b[1]));
}
__device__ __forceinline__ void cp16(uint32_t dst, const void* src) {
    asm volatile("cp.async.cg.shared.global [%0], [%1], 16;"
                 :: "r"(dst), "l"(src) : "memory");
}
#define CP_COMMIT() asm volatile("cp.async.commit_group;" ::: "memory")
#define CP_WAIT1()  asm volatile("cp.async.wait_group 1;" ::: "memory")
#define CP_WAIT0()  asm volatile("cp.async.wait_group 0;" ::: "memory")

__device__ __forceinline__ uint32_t packbf(float lo, float hi) {
    __nv_bfloat162 t = __floats2bfloat162_rn(lo, hi);
    return *(uint32_t*)&t;
}
__device__ __forceinline__ float bfhi(float v) {
    return __bfloat162float(__float2bfloat16(v));
}

// ---------------------------------------------------------------------------
// Scratch (__device__ globals — no allocations allowed)
// ---------------------------------------------------------------------------
__device__ __nv_bfloat16 g_xhi[BL * DD];
__device__ __nv_bfloat16 g_xlo[BL * DD];
__device__ __nv_bfloat16 g_ctxhi[BL * DD];
__device__ __nv_bfloat16 g_ctxlo[BL * DD];
__device__ __nv_bfloat16 g_wqt_h[DD * DD];
__device__ __nv_bfloat16 g_wqt_l[DD * DD];
__device__ __nv_bfloat16 g_wkvt_h[512 * DD];
__device__ __nv_bfloat16 g_wkvt_l[512 * DD];
__device__ __nv_bfloat16 g_wot_h[DD * DD];
__device__ __nv_bfloat16 g_wot_l[DD * DD];

__device__ __nv_bfloat16 g_qh[BL * DD];
__device__ __nv_bfloat16 g_ql[BL * DD];
__device__ __nv_bfloat16 g_kh[BL * 256];
__device__ __nv_bfloat16 g_kl[BL * 256];
__device__ __nv_bfloat16 g_vh[BL * 256];
__device__ __nv_bfloat16 g_vl[BL * 256];

__device__ float g_cos[LL * 32];
__device__ float g_sin[LL * 32];

// ---------------------------------------------------------------------------
// fp32 -> bf16 hi/lo split (for input x)
// ---------------------------------------------------------------------------
__global__ __launch_bounds__(256)
void cvt_split(const float* __restrict__ in, __nv_bfloat16* __restrict__ hi,
               __nv_bfloat16* __restrict__ lo, int n4) {
    int i = blockIdx.x * 256 + threadIdx.x;
    if (i >= n4) return;
    float4 v = ((const float4*)in)[i];
    float vv[4] = {v.x, v.y, v.z, v.w};
    __nv_bfloat16 h[4], l[4];
#pragma unroll
    for (int j = 0; j < 4; j++) {
        h[j] = __float2bfloat16(vv[j]);
        l[j] = __float2bfloat16(vv[j] - __bfloat162float(h[j]));
    }
    ((uint64_t*)hi)[i] = *(uint64_t*)h;
    ((uint64_t*)lo)[i] = *(uint64_t*)l;
}

// ---------------------------------------------------------------------------
// Batched transpose for Wq, Wk, Wv
// ---------------------------------------------------------------------------
__global__ __launch_bounds__(256)
void cvt_transpose3(const float* __restrict__ Wq, const float* __restrict__ Wk,
                    const float* __restrict__ Wv,
                    __nv_bfloat16* __restrict__ wqh, __nv_bfloat16* __restrict__ wql,
                    __nv_bfloat16* __restrict__ wkvh, __nv_bfloat16* __restrict__ wkvl) {
    __shared__ float t[32][33];
    const int z = blockIdx.z;
    const float* W;
    __nv_bfloat16 *hiT, *loT;
    int Nd, rowoff = 0;
    if (z == 0) { W = Wq; hiT = wqh; loT = wql; Nd = 1024; }
    else if (z == 1) { W = Wk; hiT = wkvh; loT = wkvl; Nd = 256; }
    else { W = Wv; hiT = wkvh; loT = wkvl; Nd = 256; rowoff = 256; }
    if (blockIdx.x * 32 >= Nd) return;

    int n0 = blockIdx.x << 5, k0 = blockIdx.y << 5;
    int tx = threadIdx.x & 31, ty = threadIdx.x >> 5;
    for (int r = ty; r < 32; r += 8)
        t[r][tx] = W[(size_t)(k0 + r) * Nd + n0 + tx];
    __syncthreads();
    for (int r = ty; r < 32; r += 8) {
        float v = t[tx][r];
        __nv_bfloat16 h = __float2bfloat16(v);
        size_t o = (size_t)(rowoff + n0 + r) * DD + k0 + tx;
        hiT[o] = h;
        loT[o] = __float2bfloat16(v - __bfloat162float(h));
    }
}

__global__ __launch_bounds__(256)
void cvt_transpose(const float* __restrict__ W, __nv_bfloat16* __restrict__ hiT,
                   __nv_bfloat16* __restrict__ loT, int Kd, int Nd) {
    __shared__ float t[32][33];
    int n0 = blockIdx.x << 5, k0 = blockIdx.y << 5;
    int tx = threadIdx.x & 31, ty = threadIdx.x >> 5;
    for (int r = ty; r < 32; r += 8)
        t[r][tx] = W[(size_t)(k0 + r) * Nd + n0 + tx];
    __syncthreads();
    for (int r = ty; r < 32; r += 8) {
        float v = t[tx][r];
        __nv_bfloat16 h = __float2bfloat16(v);
        size_t o = (size_t)(n0 + r) * Kd + k0 + tx;
        hiT[o] = h;
        loT[o] = __float2bfloat16(v - __bfloat162float(h));
    }
}

// ---------------------------------------------------------------------------
// RoPE cos/sin tables: [pos][j], pos < 2048, j < 32
// ---------------------------------------------------------------------------
__global__ __launch_bounds__(256)
void rope_tab(float* __restrict__ ct, float* __restrict__ st) {
    int i = blockIdx.x * 256 + threadIdx.x;
    if (i >= LL * 32) return;
    int pos = i >> 5, j = i & 31;
    float inv = powf(10000.0f, -(float)j * (1.0f / 32.0f));
    float s, c;
    sincosf((float)pos * inv, &s, &c);
    ct[i] = c;
    st[i] = s;
}

// ---------------------------------------------------------------------------
// QKV GEMM (mma.sync bf16x3) with fused RoPE + bf16 hi/lo split epilogue.
// grid (12, 32): bx<8 -> Q panel; bx 8..9 -> K panel; bx 10..11 -> V panel.
// ---------------------------------------------------------------------------
#define STG_BYTES 40960
#define SUB_BYTES 10240

__global__ __launch_bounds__(256, 2)
void gemm_qkv(const __nv_bfloat16* __restrict__ Ahi,
              const __nv_bfloat16* __restrict__ Alo,
              const __nv_bfloat16* __restrict__ Wqh,
              const __nv_bfloat16* __restrict__ Wql,
              const __nv_bfloat16* __restrict__ Wkvh,
              const __nv_bfloat16* __restrict__ Wkvl,
              __nv_bfloat16* __restrict__ qh, __nv_bfloat16* __restrict__ ql,
              __nv_bfloat16* __restrict__ kh, __nv_bfloat16* __restrict__ kl,
              __nv_bfloat16* __restrict__ vh, __nv_bfloat16* __restrict__ vl,
              const float* __restrict__ ct, const float* __restrict__ st) {
    extern __shared__ char sm[];
    const uint32_t smb = smem_u32(sm);
    const int K = DD;

    const int tid = threadIdx.x;
    const int lid = tid & 31;
    const int wid = tid >> 5;
    const int wm  = wid >> 1;
    const int wn  = wid & 1;
    const int row0 = blockIdx.y << 7;
    const int NCH = K >> 5;

    const bool isQ = (int)blockIdx.x < 8;
    const int col0 = isQ ? (blockIdx.x << 7) : (((int)blockIdx.x - 8) << 7);
    const __nv_bfloat16* Bhi = isQ ? Wqh : Wkvh;
    const __nv_bfloat16* Blo = isQ ? Wql : Wkvl;

    const __nv_bfloat16* srcbase[4] = {Ahi, Alo, Bhi, Blo};

    auto prefetch = [&](int c, int stage) {
#pragma unroll
        for (int it = 0; it < 8; it++) {
            int i = tid + (it << 8);
            int s = i >> 9;
            int j = i & 511;
            int r = j >> 2;
            int u = j & 3;
            int grow = (s < 2 ? row0 : col0) + r;
            const __nv_bfloat16* src =
                srcbase[s] + (size_t)grow * K + (c << 5) + (u << 3);
            uint32_t dst = smb + stage * STG_BYTES + s * SUB_BYTES
                         + r * 80 + (u << 4);
            cp16(dst, src);
        }
    };

    prefetch(0, 0); CP_COMMIT();
    prefetch(1, 1); CP_COMMIT();

    float acc[2][8][4];
#pragma unroll
    for (int a = 0; a < 2; a++)
#pragma unroll
        for (int b = 0; b < 8; b++)
#pragma unroll
            for (int d = 0; d < 4; d++) acc[a][b][d] = 0.0f;

    const uint32_t aoff = (uint32_t)((wm * 32 + (lid & 15)) * 80
                                     + ((lid >> 4) << 4));
    const uint32_t boff = (uint32_t)((wn * 64 + ((lid >> 4) << 3) + (lid & 7)) * 80
                                     + (((lid >> 3) & 1) << 4));

    for (int c = 0; c < NCH; c++) {
        CP_WAIT1();
        __syncthreads();

        const uint32_t sb = smb + (c & 1) * STG_BYTES;
        const uint32_t sa_h = sb;
        const uint32_t sa_l = sb + SUB_BYTES;
        const uint32_t sb_h = sb + 2 * SUB_BYTES;
        const uint32_t sb_l = sb + 3 * SUB_BYTES;

#pragma unroll
        for (int ks = 0; ks < 2; ks++) {
            uint32_t Ah[2][4], Al[2][4];
            ldsm4(sa_h + aoff + ks * 32, Ah[0]);
            ldsm4(sa_h + aoff + 16 * 80 + ks * 32, Ah[1]);
            ldsm4(sa_l + aoff + ks * 32, Al[0]);
            ldsm4(sa_l + aoff + 16 * 80 + ks * 32, Al[1]);
#pragma unroll
            for (int g = 0; g < 4; g++) {
                uint32_t Bh[4], Bl[4];
                ldsm4(sb_h + boff + g * (16 * 80) + ks * 32, Bh);
                ldsm4(sb_l + boff + g * (16 * 80) + ks * 32, Bl);
#pragma unroll
                for (int mi = 0; mi < 2; mi++) {
                    mma16816(acc[mi][2 * g],     Ah[mi], Bh);
                    mma16816(acc[mi][2 * g],     Ah[mi], Bl);
                    mma16816(acc[mi][2 * g],     Al[mi], Bh);
                    mma16816(acc[mi][2 * g + 1], Ah[mi], Bh + 2);
                    mma16816(acc[mi][2 * g + 1], Ah[mi], Bl + 2);
                    mma16816(acc[mi][2 * g + 1], Al[mi], Bh + 2);
                }
            }
        }
        __syncthreads();
        if (c + 2 < NCH) prefetch(c + 2, c & 1);
        CP_COMMIT();
    }

    // ---- fused epilogue: RoPE (Q,K) + hi/lo split -> bf16 outputs ----
    __nv_bfloat16 *dsth, *dstl;
    int ldd, dcol0;
    bool rope;
    if (isQ)            { dsth = qh; dstl = ql; ldd = 1024; dcol0 = col0; rope = true; }
    else if (col0 < 256){ dsth = kh; dstl = kl; ldd = 256;  dcol0 = col0; rope = true; }
    else                { dsth = vh; dstl = vl; ldd = 256;  dcol0 = col0 - 256; rope = false; }

    const int rbase = row0 + wm * 32 + (lid >> 2);
#pragma unroll
    for (int mi = 0; mi < 2; mi++) {
#pragma unroll
        for (int half = 0; half < 2; half++) {
            const int row = rbase + mi * 16 + half * 8;
            const int pos = row & (LL - 1);
            const int e0 = half * 2;
            if (rope) {
#pragma unroll
                for (int ni = 0; ni < 4; ni++) {
                    const int j0 = ni * 8 + ((lid & 3) << 1);   // 0..30 (even)
                    float c0 = ct[pos * 32 + j0],     s0 = st[pos * 32 + j0];
                    float c1 = ct[pos * 32 + j0 + 1], s1 = st[pos * 32 + j0 + 1];
                    float x1a = acc[mi][ni][e0],     x1b = acc[mi][ni][e0 + 1];
                    float x2a = acc[mi][ni + 4][e0], x2b = acc[mi][ni + 4][e0 + 1];
                    float y1a = x1a * c0 - x2a * s0;
                    float y2a = x2a * c0 + x1a * s0;
                    float y1b = x1b * c1 - x2b * s1;
                    float y2b = x2b * c1 + x1b * s1;
                    float h1a = bfhi(y1a), h1b = bfhi(y1b);
                    float h2a = bfhi(y2a), h2b = bfhi(y2b);
                    size_t o1 = (size_t)row * ldd + dcol0 + wn * 64 + j0;
                    size_t o2 = o1 + 32;
                    *(uint32_t*)&dsth[o1] = packbf(h1a, h1b);
                    *(uint32_t*)&dstl[o1] = packbf(y1a - h1a, y1b - h1b);
                    *(uint32_t*)&dsth[o2] = packbf(h2a, h2b);
                    *(uint32_t*)&dstl[o2] = packbf(y2a - h2a, y2b - h2b);
                }
            } else {
#pragma unroll
                for (int ni = 0; ni < 8; ni++) {
                    const int j0 = ni * 8 + ((lid & 3) << 1);
                    float xa = acc[mi][ni][e0], xb = acc[mi][ni][e0 + 1];
                    float ha = bfhi(xa), hb = bfhi(xb);
                    size_t o1 = (size_t)row * ldd + dcol0 + wn * 64 + j0;
                    *(uint32_t*)&dsth[o1] = packbf(ha, hb);
                    *(uint32_t*)&dstl[o1] = packbf(xa - ha, xb - hb);
                }
            }
        }
    }
}

// ---------------------------------------------------------------------------
// Plain tensor-core GEMM for the output projection (fp32 epilogue).
// ---------------------------------------------------------------------------
__global__ __launch_bounds__(256, 2)
void gemm_o(const __nv_bfloat16* __restrict__ Ahi,
            const __nv_bfloat16* __restrict__ Alo,
            const __nv_bfloat16* __restrict__ Bhi,
            const __nv_bfloat16* __restrict__ Blo,
            float* __restrict__ C, int K, int ldc) {
    extern __shared__ char sm[];
    const uint32_t smb = smem_u32(sm);

    const int tid = threadIdx.x;
    const int lid = tid & 31;
    const int wid = tid >> 5;
    const int wm  = wid >> 1;
    const int wn  = wid & 1;
    const int row0 = blockIdx.y << 7;
    const int col0 = blockIdx.x << 7;
    const int NCH = K >> 5;

    const __nv_bfloat16* srcbase[4] = {Ahi, Alo, Bhi, Blo};

    auto prefetch = [&](int c, int stage) {
#pragma unroll
        for (int it = 0; it < 8; it++) {
            int i = tid + (it << 8);
            int s = i >> 9;
            int j = i & 511;
            int r = j >> 2;
            int u = j & 3;
            int grow = (s < 2 ? row0 : col0) + r;
            const __nv_bfloat16* src =
                srcbase[s] + (size_t)grow * K + (c << 5) + (u << 3);
            uint32_t dst = smb + stage * STG_BYTES + s * SUB_BYTES
                         + r * 80 + (u << 4);
            cp16(dst, src);
        }
    };

    prefetch(0, 0); CP_COMMIT();
    prefetch(1, 1); CP_COMMIT();

    float acc[2][8][4];
#pragma unroll
    for (int a = 0; a < 2; a++)
#pragma unroll
        for (int b = 0; b < 8; b++)
#pragma unroll
            for (int d = 0; d < 4; d++) acc[a][b][d] = 0.0f;

    const uint32_t aoff = (uint32_t)((wm * 32 + (lid & 15)) * 80
                                     + ((lid >> 4) << 4));
    const uint32_t boff = (uint32_t)((wn * 64 + ((lid >> 4) << 3) + (lid & 7)) * 80
                                     + (((lid >> 3) & 1) << 4));

    for (int c = 0; c < NCH; c++) {
        CP_WAIT1();
        __syncthreads();

        const uint32_t sb = smb + (c & 1) * STG_BYTES;
        const uint32_t sa_h = sb;
        const uint32_t sa_l = sb + SUB_BYTES;
        const uint32_t sb_h = sb + 2 * SUB_BYTES;
        const uint32_t sb_l = sb + 3 * SUB_BYTES;

#pragma unroll
        for (int ks = 0; ks < 2; ks++) {
            uint32_t Ah[2][4], Al[2][4];
            ldsm4(sa_h + aoff + ks * 32, Ah[0]);
            ldsm4(sa_h + aoff + 16 * 80 + ks * 32, Ah[1]);
            ldsm4(sa_l + aoff + ks * 32, Al[0]);
            ldsm4(sa_l + aoff + 16 * 80 + ks * 32, Al[1]);
#pragma unroll
            for (int g = 0; g < 4; g++) {
                uint32_t Bh[4], Bl[4];
                ldsm4(sb_h + boff + g * (16 * 80) + ks * 32, Bh);
                ldsm4(sb_l + boff + g * (16 * 80) + ks * 32, Bl);
#pragma unroll
                for (int mi = 0; mi < 2; mi++) {
                    mma16816(acc[mi][2 * g],     Ah[mi], Bh);
                    mma16816(acc[mi][2 * g],     Ah[mi], Bl);
                    mma16816(acc[mi][2 * g],     Al[mi], Bh);
                    mma16816(acc[mi][2 * g + 1], Ah[mi], Bh + 2);
                    mma16816(acc[mi][2 * g + 1], Ah[mi], Bl + 2);
                    mma16816(acc[mi][2 * g + 1], Al[mi], Bh + 2);
                }
            }
        }
        __syncthreads();
        if (c + 2 < NCH) prefetch(c + 2, c & 1);
        CP_COMMIT();
    }

#pragma unroll
    for (int mi = 0; mi < 2; mi++) {
        int r0 = row0 + wm * 32 + mi * 16 + (lid >> 2);
#pragma unroll
        for (int ni = 0; ni < 8; ni++) {
            int cc = col0 + wn * 64 + ni * 8 + ((lid & 3) << 1);
            float2 v0; v0.x = acc[mi][ni][0]; v0.y = acc[mi][ni][1];
            float2 v1; v1.x = acc[mi][ni][2]; v1.y = acc[mi][ni][3];
            *(float2*)(C + (size_t)r0 * ldc + cc)       = v0;
            *(float2*)(C + (size_t)(r0 + 8) * ldc + cc) = v1;
        }
    }
}

// ---------------------------------------------------------------------------
// Tensor-core flash attention (round-6 mainloop; epilogue emits bf16 hi/lo
// ctx directly). 256 q-rows/CTA, 8 warps x 32 rows, 73.7KB smem.
// ---------------------------------------------------------------------------
#define AST 144
#define KVSUB (64 * AST)
#define KVSTG (4 * KVSUB)
#define QSUB  KVSTG
#define ATT_SMEM (2 * KVSTG)

__global__ __launch_bounds__(256, 1)
void attn_mma(const __nv_bfloat16* __restrict__ qh, const __nv_bfloat16* __restrict__ ql,
              const __nv_bfloat16* __restrict__ kh, const __nv_bfloat16* __restrict__ kl,
              const __nv_bfloat16* __restrict__ vh, const __nv_bfloat16* __restrict__ vl,
              __nv_bfloat16* __restrict__ cthi, __nv_bfloat16* __restrict__ ctlo) {
    extern __shared__ char sm[];
    const uint32_t smb = smem_u32(sm);

    const int tid = threadIdx.x;
    const int lid = tid & 31;
    const int wid = tid >> 5;
    const int q0  = blockIdx.x << 8;
    const int h   = blockIdx.y;
    const int b   = blockIdx.z;
    const int kvh2 = h >> 2;

    const float slope = exp2f(-0.5f * (float)(h + 1));
    const float scale = 0.125f;

    // ---- stage Q (hi at 0, lo at QSUB) through the KV buffer region ----
#pragma unroll
    for (int t = 0; t < 16; t++) {
        int i = tid + (t << 8);
        int s = i >> 11;
        int j = i & 2047;
        int r = j >> 3;
        int u = j & 7;
        const __nv_bfloat16* src =
            (s ? ql : qh) + (size_t)(b * LL + q0 + r) * 1024 + h * 64 + (u << 3);
        cp16(smb + s * QSUB + r * AST + (u << 4), src);
    }
    CP_COMMIT();
    CP_WAIT0();
    __syncthreads();

    // ---- Q fragments for both 16-row blocks -> registers ----
    uint32_t AQh[2][4][4], AQl[2][4][4];
#pragma unroll
    for (int bl = 0; bl < 2; bl++) {
        uint32_t qaddr = (uint32_t)((wid * 32 + bl * 16 + (lid & 15)) * AST
                                    + ((lid >> 4) << 4));
#pragma unroll
        for (int kt = 0; kt < 4; kt++) {
            ldsm4(smb + qaddr + kt * 32, AQh[bl][kt]);
            ldsm4(smb + QSUB + qaddr + kt * 32, AQl[bl][kt]);
        }
    }
    __syncthreads();

    // ---- KV pipeline ----
    const __nv_bfloat16* kvsrc[4] = {kh, kl, vh, vl};
    auto pf = [&](int c, int st) {
#pragma unroll
        for (int t = 0; t < 8; t++) {
            int i = tid + (t << 8);
            int s = i >> 9;
            int j = i & 511;
            int r = j >> 3;
            int u = j & 7;
            const __nv_bfloat16* src =
                kvsrc[s] + (size_t)(b * LL + (c << 6) + r) * 256 + kvh2 * 64 + (u << 3);
            cp16(smb + st * KVSTG + s * KVSUB + r * AST + (u << 4), src);
        }
    };
    pf(0, 0); CP_COMMIT();
    pf(1, 1); CP_COMMIT();

    const uint32_t kaddr = (uint32_t)((((lid >> 4) << 3) + (lid & 7)) * AST
                                      + (((lid >> 3) & 1) << 4));
    const uint32_t vaddr = (uint32_t)((lid & 15) * AST + ((lid >> 4) << 4));

    float o[2][8][4];
    float m[2][2], lsum[2][2];
#pragma unroll
    for (int bl = 0; bl < 2; bl++) {
#pragma unroll
        for (int i = 0; i < 8; i++)
#pragma unroll
            for (int e = 0; e < 4; e++) o[bl][i][e] = 0.0f;
        m[bl][0] = -1e30f; m[bl][1] = -1e30f;
        lsum[bl][0] = 0.0f; lsum[bl][1] = 0.0f;
    }

    const int NTILES = LL / 64;

    for (int c = 0; c < NTILES; c++) {
        CP_WAIT1();
        __syncthreads();

        const uint32_t sb  = smb + (c & 1) * KVSTG;
        const uint32_t skh = sb;
        const uint32_t skl = sb + KVSUB;
        const uint32_t svh = sb + 2 * KVSUB;
        const uint32_t svl = sb + 3 * KVSUB;

        float S[2][8][4];
#pragma unroll
        for (int bl = 0; bl < 2; bl++)
#pragma unroll
            for (int i = 0; i < 8; i++)
#pragma unroll
                for (int e = 0; e < 4; e++) S[bl][i][e] = 0.0f;

#pragma unroll
        for (int g = 0; g < 4; g++) {
#pragma unroll
            for (int ks = 0; ks < 4; ks++) {
                uint32_t Bh[4], Bl[4];
                uint32_t base = (g << 4) * AST + kaddr + (ks << 5);
                ldsm4(skh + base, Bh);
                ldsm4(skl + base, Bl);
#pragma unroll
                for (int bl = 0; bl < 2; bl++) {
                    mma16816(S[bl][2 * g],     AQh[bl][ks], Bh);
                    mma16816(S[bl][2 * g],     AQh[bl][ks], Bl);
                    mma16816(S[bl][2 * g],     AQl[bl][ks], Bh);
                    mma16816(S[bl][2 * g + 1], AQh[bl][ks], Bh + 2);
                    mma16816(S[bl][2 * g + 1], AQh[bl][ks], Bl + 2);
                    mma16816(S[bl][2 * g + 1], AQl[bl][ks], Bh + 2);
                }
            }
        }

        uint32_t PAh[2][4][4], PAl[2][4][4];
        const float colb = (float)((c << 6) + 2 * (lid & 3));
#pragma unroll
        for (int bl = 0; bl < 2; bl++) {
            const float qrow0 = (float)(q0 + wid * 32 + bl * 16 + (lid >> 2));
            const float qrow1 = qrow0 + 8.0f;
            const float sb0 = slope * (colb - qrow0);
            const float sb1 = slope * (colb - qrow1);
            float mx0 = -1e30f, mx1 = -1e30f;
#pragma unroll
            for (int nt = 0; nt < 8; nt++) {
                float bo = slope * (float)(nt << 3);
                S[bl][nt][0] = fmaf(S[bl][nt][0], scale, sb0 + bo);
                S[bl][nt][1] = fmaf(S[bl][nt][1], scale, sb0 + bo + slope);
                S[bl][nt][2] = fmaf(S[bl][nt][2], scale, sb1 + bo);
                S[bl][nt][3] = fmaf(S[bl][nt][3], scale, sb1 + bo + slope);
                mx0 = fmaxf(mx0, fmaxf(S[bl][nt][0], S[bl][nt][1]));
                mx1 = fmaxf(mx1, fmaxf(S[bl][nt][2], S[bl][nt][3]));
            }
            mx0 = fmaxf(mx0, __shfl_xor_sync(0xffffffffu, mx0, 1));
            mx0 = fmaxf(mx0, __shfl_xor_sync(0xffffffffu, mx0, 2));
            mx1 = fmaxf(mx1, __shfl_xor_sync(0xffffffffu, mx1, 1));
            mx1 = fmaxf(mx1, __shfl_xor_sync(0xffffffffu, mx1, 2));

            float mn0 = fmaxf(m[bl][0], mx0);
            float mn1 = fmaxf(m[bl][1], mx1);
            float corr0 = __expf(m[bl][0] - mn0);
            float corr1 = __expf(m[bl][1] - mn1);
            m[bl][0] = mn0; m[bl][1] = mn1;

            float ps0 = 0.0f, ps1 = 0.0f;
#pragma unroll
            for (int nt = 0; nt < 8; nt++) {
                S[bl][nt][0] = __expf(S[bl][nt][0] - mn0);
                S[bl][nt][1] = __expf(S[bl][nt][1] - mn0);
                S[bl][nt][2] = __expf(S[bl][nt][2] - mn1);
                S[bl][nt][3] = __expf(S[bl][nt][3] - mn1);
                ps0 += S[bl][nt][0] + S[bl][nt][1];
                ps1 += S[bl][nt][2] + S[bl][nt][3];
            }
            ps0 += __shfl_xor_sync(0xffffffffu, ps0, 1);
            ps0 += __shfl_xor_sync(0xffffffffu, ps0, 2);
            ps1 += __shfl_xor_sync(0xffffffffu, ps1, 1);
            ps1 += __shfl_xor_sync(0xffffffffu, ps1, 2);
            lsum[bl][0] = lsum[bl][0] * corr0 + ps0;
            lsum[bl][1] = lsum[bl][1] * corr1 + ps1;

#pragma unroll
            for (int nt = 0; nt < 8; nt++) {
                o[bl][nt][0] *= corr0;
                o[bl][nt][1] *= corr0;
                o[bl][nt][2] *= corr1;
                o[bl][nt][3] *= corr1;
            }

#pragma unroll
            for (int kt = 0; kt < 4; kt++) {
                float p00 = S[bl][2 * kt][0],     p01 = S[bl][2 * kt][1];
                float p02 = S[bl][2 * kt][2],     p03 = S[bl][2 * kt][3];
                float p10 = S[bl][2 * kt + 1][0], p11 = S[bl][2 * kt + 1][1];
                float p12 = S[bl][2 * kt + 1][2], p13 = S[bl][2 * kt + 1][3];
                float h00 = bfhi(p00), h01 = bfhi(p01), h02 = bfhi(p02), h03 = bfhi(p03);
                float h10 = bfhi(p10), h11 = bfhi(p11), h12 = bfhi(p12), h13 = bfhi(p13);
                PAh[bl][kt][0] = packbf(h00, h01);
                PAh[bl][kt][1] = packbf(h02, h03);
                PAh[bl][kt][2] = packbf(h10, h11);
                PAh[bl][kt][3] = packbf(h12, h13);
                PAl[bl][kt][0] = packbf(p00 - h00, p01 - h01);
                PAl[bl][kt][1] = packbf(p02 - h02, p03 - h03);
                PAl[bl][kt][2] = packbf(p10 - h10, p11 - h11);
                PAl[bl][kt][3] = packbf(p12 - h12, p13 - h13);
            }
        }

#pragma unroll
        for (int dg = 0; dg < 4; dg++) {
#pragma unroll
            for (int kt = 0; kt < 4; kt++) {
                uint32_t Bvh[4], Bvl[4];
                uint32_t base = (kt << 4) * AST + vaddr + (dg << 5);
                ldsm4t(svh + base, Bvh);
                ldsm4t(svl + base, Bvl);
#pragma unroll
                for (int bl = 0; bl < 2; bl++) {
                    mma16816(o[bl][2 * dg],     PAh[bl][kt], Bvh);
                    mma16816(o[bl][2 * dg],     PAh[bl][kt], Bvl);
                    mma16816(o[bl][2 * dg],     PAl[bl][kt], Bvh);
                    mma16816(o[bl][2 * dg + 1], PAh[bl][kt], Bvh + 2);
                    mma16816(o[bl][2 * dg + 1], PAh[bl][kt], Bvl + 2);
                    mma16816(o[bl][2 * dg + 1], PAl[bl][kt], Bvh + 2);
                }
            }
        }

        __syncthreads();
        if (c + 2 < NTILES) pf(c + 2, c & 1);
        CP_COMMIT();
    }

    // ---- epilogue: normalize + bf16 hi/lo split directly to ctx ----
#pragma unroll
    for (int bl = 0; bl < 2; bl++) {
        float inv0 = 1.0f / lsum[bl][0];
        float inv1 = 1.0f / lsum[bl][1];
        const int r0 = b * LL + q0 + wid * 32 + bl * 16 + (lid >> 2);
#pragma unroll
        for (int nt = 0; nt < 8; nt++) {
            int cc = h * 64 + nt * 8 + ((lid & 3) << 1);
            float v0 = o[bl][nt][0] * inv0, v1 = o[bl][nt][1] * inv0;
            float v2 = o[bl][nt][2] * inv1, v3 = o[bl][nt][3] * inv1;
            float h0 = bfhi(v0), h1 = bfhi(v1), h2 = bfhi(v2), h3 = bfhi(v3);
            size_t oa = (size_t)r0 * 1024 + cc;
            size_t ob = (size_t)(r0 + 8) * 1024 + cc;
            *(uint32_t*)&cthi[oa] = packbf(h0, h1);
            *(uint32_t*)&ctlo[oa] = packbf(v0 - h0, v1 - h1);
            *(uint32_t*)&cthi[ob] = packbf(h2, h3);
            *(uint32_t*)&ctlo[ob] = packbf(v2 - h2, v3 - h3);
        }
    }
}

// ---------------------------------------------------------------------------
// kernel_launch
// Launch order (ncu captures index 5 = attn_mma):
//   0 cvt_split(x)  1 cvt_transpose3  2 cvt_transpose(Wo)  3 rope_tab
//   4 gemm_qkv(fused rope+split)  5 attn_mma  6 gemm_o
// ---------------------------------------------------------------------------
extern "C" void kernel_launch(void* const* d_in, const int* in_sizes, int n_in,
                              void* d_out, int out_size) {
    const float* x  = (const float*)d_in[0];
    const float* Wq = (const float*)d_in[1];
    const float* Wk = (const float*)d_in[2];
    const float* Wv = (const float*)d_in[3];
    const float* Wo = (const float*)d_in[4];
    float* out = (float*)d_out;

    __nv_bfloat16 *xhi, *xlo, *cthi, *ctlo;
    __nv_bfloat16 *wqh, *wql, *wkvh, *wkvl, *woh, *wol;
    __nv_bfloat16 *aqh, *aql, *akh, *akl, *avh, *avl;
    float *ct, *st;
    cudaGetSymbolAddress((void**)&xhi,  g_xhi);
    cudaGetSymbolAddress((void**)&xlo,  g_xlo);
    cudaGetSymbolAddress((void**)&cthi, g_ctxhi);
    cudaGetSymbolAddress((void**)&ctlo, g_ctxlo);
    cudaGetSymbolAddress((void**)&wqh,  g_wqt_h);
    cudaGetSymbolAddress((void**)&wql,  g_wqt_l);
    cudaGetSymbolAddress((void**)&wkvh, g_wkvt_h);
    cudaGetSymbolAddress((void**)&wkvl, g_wkvt_l);
    cudaGetSymbolAddress((void**)&woh,  g_wot_h);
    cudaGetSymbolAddress((void**)&wol,  g_wot_l);
    cudaGetSymbolAddress((void**)&aqh,  g_qh);
    cudaGetSymbolAddress((void**)&aql,  g_ql);
    cudaGetSymbolAddress((void**)&akh,  g_kh);
    cudaGetSymbolAddress((void**)&akl,  g_kl);
    cudaGetSymbolAddress((void**)&avh,  g_vh);
    cudaGetSymbolAddress((void**)&avl,  g_vl);
    cudaGetSymbolAddress((void**)&ct,   g_cos);
    cudaGetSymbolAddress((void**)&st,   g_sin);

    const int smem_gemm = 2 * STG_BYTES;
    cudaFuncSetAttribute(gemm_qkv, cudaFuncAttributeMaxDynamicSharedMemorySize,
                         smem_gemm);
    cudaFuncSetAttribute(gemm_o, cudaFuncAttributeMaxDynamicSharedMemorySize,
                         smem_gemm);
    cudaFuncSetAttribute(attn_mma, cudaFuncAttributeMaxDynamicSharedMemorySize,
                         ATT_SMEM);

    dim3 blk(256);

    // 0: x split
    cvt_split<<<(BL * DD / 4 + 255) / 256, blk>>>(x, xhi, xlo, BL * DD / 4);
    // 1: Wq/Wk/Wv transpose+split
    cvt_transpose3<<<dim3(32, 32, 3), blk>>>(Wq, Wk, Wv, wqh, wql, wkvh, wkvl);
    // 2: Wo transpose+split
    cvt_transpose<<<dim3(32, 32), blk>>>(Wo, woh, wol, DD, DD);
    // 3: rope tables
    rope_tab<<<(LL * 32 + 255) / 256, blk>>>(ct, st);

    // 4: QKV projection with fused RoPE + bf16 split epilogue
    gemm_qkv<<<dim3(12, BL / 128), blk, smem_gemm>>>(
        xhi, xlo, wqh, wql, wkvh, wkvl, aqh, aql, akh, akl, avh, avl, ct, st);

    // 5: tensor-core attention (emits bf16 hi/lo ctx)  <-- ncu capture slot
    attn_mma<<<dim3(LL / 256, HH, BB), blk, ATT_SMEM>>>(
        aqh, aql, akh, akl, avh, avl, cthi, ctlo);

    // 6: output projection
    gemm_o<<<dim3(8, BL / 128), blk, smem_gemm>>>(
        cthi, ctlo, woh, wol, out, DD, DD);
}

// round 10
// speedup vs baseline: 1.5948x; 1.0661x over previous
#include <cuda_runtime.h>
#include <cuda_bf16.h>
#include <math.h>
#include <stdint.h>

// Problem constants
#define BB   2
#define LL   2048
#define DD   1024
#define HH   16
#define KVH  4
#define HDIM 64
#define BL   (BB * LL)    // 4096

typedef unsigned long long ull;

// ---------------------------------------------------------------------------
// mma.sync / ldmatrix / cp.async helpers (baseline PTX ISA)
// ---------------------------------------------------------------------------
__device__ __forceinline__ uint32_t smem_u32(const void* p) {
    uint32_t a;
    asm("{ .reg .u64 t; cvta.to.shared.u64 t, %1; cvt.u32.u64 %0, t; }"
        : "=r"(a) : "l"(p));
    return a;
}
__device__ __forceinline__ void ldsm4(uint32_t addr, uint32_t* r) {
    asm volatile("ldmatrix.sync.aligned.m8n8.x4.shared.b16 {%0,%1,%2,%3}, [%4];"
                 : "=r"(r[0]), "=r"(r[1]), "=r"(r[2]), "=r"(r[3]) : "r"(addr));
}
__device__ __forceinline__ void ldsm4t(uint32_t addr, uint32_t* r) {
    asm volatile("ldmatrix.sync.aligned.m8n8.x4.trans.shared.b16 {%0,%1,%2,%3}, [%4];"
                 : "=r"(r[0]), "=r"(r[1]), "=r"(r[2]), "=r"(r[3]) : "r"(addr));
}
__device__ __forceinline__ void mma16816(float* d, const uint32_t* a,
                                         const uint32_t* b) {
    asm volatile(
        "mma.sync.aligned.m16n8k16.row.col.f32.bf16.bf16.f32 "
        "{%0,%1,%2,%3}, {%4,%5,%6,%7}, {%8,%9}, {%0,%1,%2,%3};"
        : "+f"(d[0]), "+f"(d[1]), "+f"(d[2]), "+f"(d[3])
        : "r"(a[0]), "r"(a[1]), "r"(a[2]), "r"(a[3]), "r"(b[0]), "r"(b[1]));
}
__device__ __forceinline__ void cp16(uint32_t dst, const void* src) {
    asm volatile("cp.async.cg.shared.global [%0], [%1], 16;"
                 :: "r"(dst), "l"(src) : "memory");
}
#define CP_COMMIT() asm volatile("cp.async.commit_group;" ::: "memory")
#define CP_WAIT1()  asm volatile("cp.async.wait_group 1;" ::: "memory")
#define CP_WAIT0()  asm volatile("cp.async.wait_group 0;" ::: "memory")

__device__ __forceinline__ uint32_t packbf(float lo, float hi) {
    __nv_bfloat162 t = __floats2bfloat162_rn(lo, hi);
    return *(uint32_t*)&t;
}
__device__ __forceinline__ float bfhi(float v) {
    return __bfloat162float(__float2bfloat16(v));
}

// ---------------------------------------------------------------------------
// Scratch (__device__ globals — no allocations allowed)
// ---------------------------------------------------------------------------
__device__ __nv_bfloat16 g_xhi[BL * DD];
__device__ __nv_bfloat16 g_xlo[BL * DD];
__device__ __nv_bfloat16 g_ctxhi[BL * DD];
__device__ __nv_bfloat16 g_ctxlo[BL * DD];
__device__ __nv_bfloat16 g_wqt_h[DD * DD];
__device__ __nv_bfloat16 g_wqt_l[DD * DD];
__device__ __nv_bfloat16 g_wkvt_h[512 * DD];
__device__ __nv_bfloat16 g_wkvt_l[512 * DD];
__device__ __nv_bfloat16 g_wot_h[DD * DD];
__device__ __nv_bfloat16 g_wot_l[DD * DD];

__device__ __nv_bfloat16 g_qh[BL * DD];
__device__ __nv_bfloat16 g_ql[BL * DD];
__device__ __nv_bfloat16 g_kh[BL * 256];
__device__ __nv_bfloat16 g_kl[BL * 256];
__device__ __nv_bfloat16 g_vh[BL * 256];
__device__ __nv_bfloat16 g_vl[BL * 256];

__device__ float g_cos[LL * 32];
__device__ float g_sin[LL * 32];

// ---------------------------------------------------------------------------
// Fused preprocessing: one launch, block-dispatched.
//   blocks [0, 4096)        : x fp32 -> bf16 hi/lo split
//   blocks [4096, 5632)     : Wq/Wk/Wv transpose+split
//   blocks [5632, 6656)     : Wo transpose+split
//   blocks [6656, 6912)     : rope tables
// ---------------------------------------------------------------------------
#define PREP_SPLIT   4096
#define PREP_T3      (PREP_SPLIT + 1536)    // 5632
#define PREP_WO      (PREP_T3 + 1024)       // 6656
#define PREP_TOTAL   (PREP_WO + 256)        // 6912

__global__ __launch_bounds__(256)
void prep(const float* __restrict__ x,
          const float* __restrict__ Wq, const float* __restrict__ Wk,
          const float* __restrict__ Wv, const float* __restrict__ Wo,
          __nv_bfloat16* __restrict__ xhi, __nv_bfloat16* __restrict__ xlo,
          __nv_bfloat16* __restrict__ wqh, __nv_bfloat16* __restrict__ wql,
          __nv_bfloat16* __restrict__ wkvh, __nv_bfloat16* __restrict__ wkvl,
          __nv_bfloat16* __restrict__ woh, __nv_bfloat16* __restrict__ wol,
          float* __restrict__ ct, float* __restrict__ st) {
    __shared__ float t[32][33];
    const int bid = blockIdx.x;

    if (bid < PREP_SPLIT) {
        // x split: 4 fp32 per thread
        int i = bid * 256 + threadIdx.x;
        float4 v = ((const float4*)x)[i];
        float vv[4] = {v.x, v.y, v.z, v.w};
        __nv_bfloat16 h[4], l[4];
#pragma unroll
        for (int j = 0; j < 4; j++) {
            h[j] = __float2bfloat16(vv[j]);
            l[j] = __float2bfloat16(vv[j] - __bfloat162float(h[j]));
        }
        ((uint64_t*)xhi)[i] = *(uint64_t*)h;
        ((uint64_t*)xlo)[i] = *(uint64_t*)l;
        return;
    }

    if (bid < PREP_WO) {
        // transposes
        const float* W;
        __nv_bfloat16 *hiT, *loT;
        int Nd, rowoff = 0, bx, by;
        if (bid < PREP_T3) {
            int j = bid - PREP_SPLIT;
            if (j < 1024) { W = Wq; hiT = wqh; loT = wql; Nd = 1024;
                            bx = j & 31; by = j >> 5; }
            else {
                int j2 = j - 1024;            // 0..511
                int z = j2 >> 8;              // 0 -> Wk, 1 -> Wv
                int r = j2 & 255;
                bx = r & 7; by = r >> 3;
                Nd = 256;
                hiT = wkvh; loT = wkvl;
                if (z == 0) { W = Wk; }
                else        { W = Wv; rowoff = 256; }
            }
        } else {
            int j = bid - PREP_T3;
            W = Wo; hiT = woh; loT = wol; Nd = 1024;
            bx = j & 31; by = j >> 5;
        }
        int n0 = bx << 5, k0 = by << 5;
        int tx = threadIdx.x & 31, ty = threadIdx.x >> 5;
        for (int r = ty; r < 32; r += 8)
            t[r][tx] = W[(size_t)(k0 + r) * Nd + n0 + tx];
        __syncthreads();
        for (int r = ty; r < 32; r += 8) {
            float v = t[tx][r];
            __nv_bfloat16 h = __float2bfloat16(v);
            size_t o = (size_t)(rowoff + n0 + r) * DD + k0 + tx;
            hiT[o] = h;
            loT[o] = __float2bfloat16(v - __bfloat162float(h));
        }
        return;
    }

    // rope tables
    {
        int i = (bid - PREP_WO) * 256 + threadIdx.x;
        int pos = i >> 5, j = i & 31;
        float inv = powf(10000.0f, -(float)j * (1.0f / 32.0f));
        float s, c;
        sincosf((float)pos * inv, &s, &c);
        ct[i] = c;
        st[i] = s;
    }
}

// ---------------------------------------------------------------------------
// QKV GEMM (mma.sync bf16x3) with fused RoPE + bf16 hi/lo split epilogue.
// ---------------------------------------------------------------------------
#define STG_BYTES 40960
#define SUB_BYTES 10240

__global__ __launch_bounds__(256, 2)
void gemm_qkv(const __nv_bfloat16* __restrict__ Ahi,
              const __nv_bfloat16* __restrict__ Alo,
              const __nv_bfloat16* __restrict__ Wqh,
              const __nv_bfloat16* __restrict__ Wql,
              const __nv_bfloat16* __restrict__ Wkvh,
              const __nv_bfloat16* __restrict__ Wkvl,
              __nv_bfloat16* __restrict__ qh, __nv_bfloat16* __restrict__ ql,
              __nv_bfloat16* __restrict__ kh, __nv_bfloat16* __restrict__ kl,
              __nv_bfloat16* __restrict__ vh, __nv_bfloat16* __restrict__ vl,
              const float* __restrict__ ct, const float* __restrict__ st) {
    extern __shared__ char sm[];
    const uint32_t smb = smem_u32(sm);
    const int K = DD;

    const int tid = threadIdx.x;
    const int lid = tid & 31;
    const int wid = tid >> 5;
    const int wm  = wid >> 1;
    const int wn  = wid & 1;
    const int row0 = blockIdx.y << 7;
    const int NCH = K >> 5;

    const bool isQ = (int)blockIdx.x < 8;
    const int col0 = isQ ? (blockIdx.x << 7) : (((int)blockIdx.x - 8) << 7);
    const __nv_bfloat16* Bhi = isQ ? Wqh : Wkvh;
    const __nv_bfloat16* Blo = isQ ? Wql : Wkvl;

    const __nv_bfloat16* srcbase[4] = {Ahi, Alo, Bhi, Blo};

    auto prefetch = [&](int c, int stage) {
#pragma unroll
        for (int it = 0; it < 8; it++) {
            int i = tid + (it << 8);
            int s = i >> 9;
            int j = i & 511;
            int r = j >> 2;
            int u = j & 3;
            int grow = (s < 2 ? row0 : col0) + r;
            const __nv_bfloat16* src =
                srcbase[s] + (size_t)grow * K + (c << 5) + (u << 3);
            uint32_t dst = smb + stage * STG_BYTES + s * SUB_BYTES
                         + r * 80 + (u << 4);
            cp16(dst, src);
        }
    };

    prefetch(0, 0); CP_COMMIT();
    prefetch(1, 1); CP_COMMIT();

    float acc[2][8][4];
#pragma unroll
    for (int a = 0; a < 2; a++)
#pragma unroll
        for (int b = 0; b < 8; b++)
#pragma unroll
            for (int d = 0; d < 4; d++) acc[a][b][d] = 0.0f;

    const uint32_t aoff = (uint32_t)((wm * 32 + (lid & 15)) * 80
                                     + ((lid >> 4) << 4));
    const uint32_t boff = (uint32_t)((wn * 64 + ((lid >> 4) << 3) + (lid & 7)) * 80
                                     + (((lid >> 3) & 1) << 4));

    for (int c = 0; c < NCH; c++) {
        CP_WAIT1();
        __syncthreads();

        const uint32_t sb = smb + (c & 1) * STG_BYTES;
        const uint32_t sa_h = sb;
        const uint32_t sa_l = sb + SUB_BYTES;
        const uint32_t sb_h = sb + 2 * SUB_BYTES;
        const uint32_t sb_l = sb + 3 * SUB_BYTES;

#pragma unroll
        for (int ks = 0; ks < 2; ks++) {
            uint32_t Ah[2][4], Al[2][4];
            ldsm4(sa_h + aoff + ks * 32, Ah[0]);
            ldsm4(sa_h + aoff + 16 * 80 + ks * 32, Ah[1]);
            ldsm4(sa_l + aoff + ks * 32, Al[0]);
            ldsm4(sa_l + aoff + 16 * 80 + ks * 32, Al[1]);
#pragma unroll
            for (int g = 0; g < 4; g++) {
                uint32_t Bh[4], Bl[4];
                ldsm4(sb_h + boff + g * (16 * 80) + ks * 32, Bh);
                ldsm4(sb_l + boff + g * (16 * 80) + ks * 32, Bl);
#pragma unroll
                for (int mi = 0; mi < 2; mi++) {
                    mma16816(acc[mi][2 * g],     Ah[mi], Bh);
                    mma16816(acc[mi][2 * g],     Ah[mi], Bl);
                    mma16816(acc[mi][2 * g],     Al[mi], Bh);
                    mma16816(acc[mi][2 * g + 1], Ah[mi], Bh + 2);
                    mma16816(acc[mi][2 * g + 1], Ah[mi], Bl + 2);
                    mma16816(acc[mi][2 * g + 1], Al[mi], Bh + 2);
                }
            }
        }
        __syncthreads();
        if (c + 2 < NCH) prefetch(c + 2, c & 1);
        CP_COMMIT();
    }

    // ---- fused epilogue: RoPE (Q,K) + hi/lo split -> bf16 outputs ----
    __nv_bfloat16 *dsth, *dstl;
    int ldd, dcol0;
    bool rope;
    if (isQ)            { dsth = qh; dstl = ql; ldd = 1024; dcol0 = col0; rope = true; }
    else if (col0 < 256){ dsth = kh; dstl = kl; ldd = 256;  dcol0 = col0; rope = true; }
    else                { dsth = vh; dstl = vl; ldd = 256;  dcol0 = col0 - 256; rope = false; }

    const int rbase = row0 + wm * 32 + (lid >> 2);
#pragma unroll
    for (int mi = 0; mi < 2; mi++) {
#pragma unroll
        for (int half = 0; half < 2; half++) {
            const int row = rbase + mi * 16 + half * 8;
            const int pos = row & (LL - 1);
            const int e0 = half * 2;
            if (rope) {
#pragma unroll
                for (int ni = 0; ni < 4; ni++) {
                    const int j0 = ni * 8 + ((lid & 3) << 1);
                    float c0 = ct[pos * 32 + j0],     s0 = st[pos * 32 + j0];
                    float c1 = ct[pos * 32 + j0 + 1], s1 = st[pos * 32 + j0 + 1];
                    float x1a = acc[mi][ni][e0],     x1b = acc[mi][ni][e0 + 1];
                    float x2a = acc[mi][ni + 4][e0], x2b = acc[mi][ni + 4][e0 + 1];
                    float y1a = x1a * c0 - x2a * s0;
                    float y2a = x2a * c0 + x1a * s0;
                    float y1b = x1b * c1 - x2b * s1;
                    float y2b = x2b * c1 + x1b * s1;
                    float h1a = bfhi(y1a), h1b = bfhi(y1b);
                    float h2a = bfhi(y2a), h2b = bfhi(y2b);
                    size_t o1 = (size_t)row * ldd + dcol0 + wn * 64 + j0;
                    size_t o2 = o1 + 32;
                    *(uint32_t*)&dsth[o1] = packbf(h1a, h1b);
                    *(uint32_t*)&dstl[o1] = packbf(y1a - h1a, y1b - h1b);
                    *(uint32_t*)&dsth[o2] = packbf(h2a, h2b);
                    *(uint32_t*)&dstl[o2] = packbf(y2a - h2a, y2b - h2b);
                }
            } else {
#pragma unroll
                for (int ni = 0; ni < 8; ni++) {
                    const int j0 = ni * 8 + ((lid & 3) << 1);
                    float xa = acc[mi][ni][e0], xb = acc[mi][ni][e0 + 1];
                    float ha = bfhi(xa), hb = bfhi(xb);
                    size_t o1 = (size_t)row * ldd + dcol0 + wn * 64 + j0;
                    *(uint32_t*)&dsth[o1] = packbf(ha, hb);
                    *(uint32_t*)&dstl[o1] = packbf(xa - ha, xb - hb);
                }
            }
        }
    }
}

// ---------------------------------------------------------------------------
// Plain tensor-core GEMM for the output projection (fp32 epilogue).
// ---------------------------------------------------------------------------
__global__ __launch_bounds__(256, 2)
void gemm_o(const __nv_bfloat16* __restrict__ Ahi,
            const __nv_bfloat16* __restrict__ Alo,
            const __nv_bfloat16* __restrict__ Bhi,
            const __nv_bfloat16* __restrict__ Blo,
            float* __restrict__ C, int K, int ldc) {
    extern __shared__ char sm[];
    const uint32_t smb = smem_u32(sm);

    const int tid = threadIdx.x;
    const int lid = tid & 31;
    const int wid = tid >> 5;
    const int wm  = wid >> 1;
    const int wn  = wid & 1;
    const int row0 = blockIdx.y << 7;
    const int col0 = blockIdx.x << 7;
    const int NCH = K >> 5;

    const __nv_bfloat16* srcbase[4] = {Ahi, Alo, Bhi, Blo};

    auto prefetch = [&](int c, int stage) {
#pragma unroll
        for (int it = 0; it < 8; it++) {
            int i = tid + (it << 8);
            int s = i >> 9;
            int j = i & 511;
            int r = j >> 2;
            int u = j & 3;
            int grow = (s < 2 ? row0 : col0) + r;
            const __nv_bfloat16* src =
                srcbase[s] + (size_t)grow * K + (c << 5) + (u << 3);
            uint32_t dst = smb + stage * STG_BYTES + s * SUB_BYTES
                         + r * 80 + (u << 4);
            cp16(dst, src);
        }
    };

    prefetch(0, 0); CP_COMMIT();
    prefetch(1, 1); CP_COMMIT();

    float acc[2][8][4];
#pragma unroll
    for (int a = 0; a < 2; a++)
#pragma unroll
        for (int b = 0; b < 8; b++)
#pragma unroll
            for (int d = 0; d < 4; d++) acc[a][b][d] = 0.0f;

    const uint32_t aoff = (uint32_t)((wm * 32 + (lid & 15)) * 80
                                     + ((lid >> 4) << 4));
    const uint32_t boff = (uint32_t)((wn * 64 + ((lid >> 4) << 3) + (lid & 7)) * 80
                                     + (((lid >> 3) & 1) << 4));

    for (int c = 0; c < NCH; c++) {
        CP_WAIT1();
        __syncthreads();

        const uint32_t sb = smb + (c & 1) * STG_BYTES;
        const uint32_t sa_h = sb;
        const uint32_t sa_l = sb + SUB_BYTES;
        const uint32_t sb_h = sb + 2 * SUB_BYTES;
        const uint32_t sb_l = sb + 3 * SUB_BYTES;

#pragma unroll
        for (int ks = 0; ks < 2; ks++) {
            uint32_t Ah[2][4], Al[2][4];
            ldsm4(sa_h + aoff + ks * 32, Ah[0]);
            ldsm4(sa_h + aoff + 16 * 80 + ks * 32, Ah[1]);
            ldsm4(sa_l + aoff + ks * 32, Al[0]);
            ldsm4(sa_l + aoff + 16 * 80 + ks * 32, Al[1]);
#pragma unroll
            for (int g = 0; g < 4; g++) {
                uint32_t Bh[4], Bl[4];
                ldsm4(sb_h + boff + g * (16 * 80) + ks * 32, Bh);
                ldsm4(sb_l + boff + g * (16 * 80) + ks * 32, Bl);
#pragma unroll
                for (int mi = 0; mi < 2; mi++) {
                    mma16816(acc[mi][2 * g],     Ah[mi], Bh);
                    mma16816(acc[mi][2 * g],     Ah[mi], Bl);
                    mma16816(acc[mi][2 * g],     Al[mi], Bh);
                    mma16816(acc[mi][2 * g + 1], Ah[mi], Bh + 2);
                    mma16816(acc[mi][2 * g + 1], Ah[mi], Bl + 2);
                    mma16816(acc[mi][2 * g + 1], Al[mi], Bh + 2);
                }
            }
        }
        __syncthreads();
        if (c + 2 < NCH) prefetch(c + 2, c & 1);
        CP_COMMIT();
    }

#pragma unroll
    for (int mi = 0; mi < 2; mi++) {
        int r0 = row0 + wm * 32 + mi * 16 + (lid >> 2);
#pragma unroll
        for (int ni = 0; ni < 8; ni++) {
            int cc = col0 + wn * 64 + ni * 8 + ((lid & 3) << 1);
            float2 v0; v0.x = acc[mi][ni][0]; v0.y = acc[mi][ni][1];
            float2 v1; v1.x = acc[mi][ni][2]; v1.y = acc[mi][ni][3];
            *(float2*)(C + (size_t)r0 * ldc + cc)       = v0;
            *(float2*)(C + (size_t)(r0 + 8) * ldc + cc) = v1;
        }
    }
}

// ---------------------------------------------------------------------------
// Tensor-core flash attention with ANALYTIC-MAX softmax (no online max):
//   m(q,h) = slope*(2047 - qpos) + 8  =>  folded bias depends only on k:
//   s' = qk*scale + slope*(k - 2047) - 8.  exp(s') in [e^-1456, ~e^0]:
//   no overflow (needs qk/8 > 96, impossible by Cauchy-Schwarz), far keys
//   underflow to exactly-correct 0, normalization cancels the shift.
//   No max-reduce, no corr, no o-rescale; lsum reduced once in epilogue.
// ---------------------------------------------------------------------------
#define AST 144
#define KVSUB (64 * AST)
#define KVSTG (4 * KVSUB)
#define QSUB  KVSTG
#define ATT_SMEM (2 * KVSTG)

__global__ __launch_bounds__(256, 1)
void attn_mma(const __nv_bfloat16* __restrict__ qh, const __nv_bfloat16* __restrict__ ql,
              const __nv_bfloat16* __restrict__ kh, const __nv_bfloat16* __restrict__ kl,
              const __nv_bfloat16* __restrict__ vh, const __nv_bfloat16* __restrict__ vl,
              __nv_bfloat16* __restrict__ cthi, __nv_bfloat16* __restrict__ ctlo) {
    extern __shared__ char sm[];
    const uint32_t smb = smem_u32(sm);

    const int tid = threadIdx.x;
    const int lid = tid & 31;
    const int wid = tid >> 5;
    const int q0  = blockIdx.x << 8;
    const int h   = blockIdx.y;
    const int b   = blockIdx.z;
    const int kvh2 = h >> 2;

    const float slope = exp2f(-0.5f * (float)(h + 1));
    const float scale = 0.125f;

    // ---- stage Q (hi at 0, lo at QSUB) through the KV buffer region ----
#pragma unroll
    for (int t = 0; t < 16; t++) {
        int i = tid + (t << 8);
        int s = i >> 11;
        int j = i & 2047;
        int r = j >> 3;
        int u = j & 7;
        const __nv_bfloat16* src =
            (s ? ql : qh) + (size_t)(b * LL + q0 + r) * 1024 + h * 64 + (u << 3);
        cp16(smb + s * QSUB + r * AST + (u << 4), src);
    }
    CP_COMMIT();
    CP_WAIT0();
    __syncthreads();

    // ---- Q fragments for both 16-row blocks -> registers ----
    uint32_t AQh[2][4][4], AQl[2][4][4];
#pragma unroll
    for (int bl = 0; bl < 2; bl++) {
        uint32_t qaddr = (uint32_t)((wid * 32 + bl * 16 + (lid & 15)) * AST
                                    + ((lid >> 4) << 4));
#pragma unroll
        for (int kt = 0; kt < 4; kt++) {
            ldsm4(smb + qaddr + kt * 32, AQh[bl][kt]);
            ldsm4(smb + QSUB + qaddr + kt * 32, AQl[bl][kt]);
        }
    }
    __syncthreads();

    // ---- KV pipeline ----
    const __nv_bfloat16* kvsrc[4] = {kh, kl, vh, vl};
    auto pf = [&](int c, int st) {
#pragma unroll
        for (int t = 0; t < 8; t++) {
            int i = tid + (t << 8);
            int s = i >> 9;
            int j = i & 511;
            int r = j >> 3;
            int u = j & 7;
            const __nv_bfloat16* src =
                kvsrc[s] + (size_t)(b * LL + (c << 6) + r) * 256 + kvh2 * 64 + (u << 3);
            cp16(smb + st * KVSTG + s * KVSUB + r * AST + (u << 4), src);
        }
    };
    pf(0, 0); CP_COMMIT();
    pf(1, 1); CP_COMMIT();

    const uint32_t kaddr = (uint32_t)((((lid >> 4) << 3) + (lid & 7)) * AST
                                      + (((lid >> 3) & 1) << 4));
    const uint32_t vaddr = (uint32_t)((lid & 15) * AST + ((lid >> 4) << 4));

    float o[2][8][4];
    float lsum[2][2];
#pragma unroll
    for (int bl = 0; bl < 2; bl++) {
#pragma unroll
        for (int i = 0; i < 8; i++)
#pragma unroll
            for (int e = 0; e < 4; e++) o[bl][i][e] = 0.0f;
        lsum[bl][0] = 0.0f; lsum[bl][1] = 0.0f;
    }

    const int NTILES = LL / 64;

    for (int c = 0; c < NTILES; c++) {
        CP_WAIT1();
        __syncthreads();

        const uint32_t sb  = smb + (c & 1) * KVSTG;
        const uint32_t skh = sb;
        const uint32_t skl = sb + KVSUB;
        const uint32_t svh = sb + 2 * KVSUB;
        const uint32_t svl = sb + 3 * KVSUB;

        float S[2][8][4];
#pragma unroll
        for (int bl = 0; bl < 2; bl++)
#pragma unroll
            for (int i = 0; i < 8; i++)
#pragma unroll
                for (int e = 0; e < 4; e++) S[bl][i][e] = 0.0f;

#pragma unroll
        for (int g = 0; g < 4; g++) {
#pragma unroll
            for (int ks = 0; ks < 4; ks++) {
                uint32_t Bh[4], Bl[4];
                uint32_t base = (g << 4) * AST + kaddr + (ks << 5);
                ldsm4(skh + base, Bh);
                ldsm4(skl + base, Bl);
#pragma unroll
                for (int bl = 0; bl < 2; bl++) {
                    mma16816(S[bl][2 * g],     AQh[bl][ks], Bh);
                    mma16816(S[bl][2 * g],     AQh[bl][ks], Bl);
                    mma16816(S[bl][2 * g],     AQl[bl][ks], Bh);
                    mma16816(S[bl][2 * g + 1], AQh[bl][ks], Bh + 2);
                    mma16816(S[bl][2 * g + 1], AQh[bl][ks], Bl + 2);
                    mma16816(S[bl][2 * g + 1], AQl[bl][ks], Bh + 2);
                }
            }
        }

        // ---- softmax with analytic max bound (q-independent bias) ----
        // bias(k) = slope*(k - 2047) - 8, k = c*64 + nt*8 + 2*(lid&3) (+1)
        uint32_t PAh[2][4][4], PAl[2][4][4];
        const float bias00 =
            slope * ((float)((c << 6) + 2 * (lid & 3)) - 2047.0f) - 8.0f;
#pragma unroll
        for (int bl = 0; bl < 2; bl++) {
#pragma unroll
            for (int nt = 0; nt < 8; nt++) {
                const float be = bias00 + slope * (float)(nt << 3);
                const float bo = be + slope;
                float p0 = __expf(fmaf(S[bl][nt][0], scale, be));
                float p1 = __expf(fmaf(S[bl][nt][1], scale, bo));
                float p2 = __expf(fmaf(S[bl][nt][2], scale, be));
                float p3 = __expf(fmaf(S[bl][nt][3], scale, bo));
                lsum[bl][0] += p0 + p1;
                lsum[bl][1] += p2 + p3;
                S[bl][nt][0] = p0; S[bl][nt][1] = p1;
                S[bl][nt][2] = p2; S[bl][nt][3] = p3;
            }

#pragma unroll
            for (int kt = 0; kt < 4; kt++) {
                float p00 = S[bl][2 * kt][0],     p01 = S[bl][2 * kt][1];
                float p02 = S[bl][2 * kt][2],     p03 = S[bl][2 * kt][3];
                float p10 = S[bl][2 * kt + 1][0], p11 = S[bl][2 * kt + 1][1];
                float p12 = S[bl][2 * kt + 1][2], p13 = S[bl][2 * kt + 1][3];
                float h00 = bfhi(p00), h01 = bfhi(p01), h02 = bfhi(p02), h03 = bfhi(p03);
                float h10 = bfhi(p10), h11 = bfhi(p11), h12 = bfhi(p12), h13 = bfhi(p13);
                PAh[bl][kt][0] = packbf(h00, h01);
                PAh[bl][kt][1] = packbf(h02, h03);
                PAh[bl][kt][2] = packbf(h10, h11);
                PAh[bl][kt][3] = packbf(h12, h13);
                PAl[bl][kt][0] = packbf(p00 - h00, p01 - h01);
                PAl[bl][kt][1] = packbf(p02 - h02, p03 - h03);
                PAl[bl][kt][2] = packbf(p10 - h10, p11 - h11);
                PAl[bl][kt][3] = packbf(p12 - h12, p13 - h13);
            }
        }

        // ---- O += P @ V ----
#pragma unroll
        for (int dg = 0; dg < 4; dg++) {
#pragma unroll
            for (int kt = 0; kt < 4; kt++) {
                uint32_t Bvh[4], Bvl[4];
                uint32_t base = (kt << 4) * AST + vaddr + (dg << 5);
                ldsm4t(svh + base, Bvh);
                ldsm4t(svl + base, Bvl);
#pragma unroll
                for (int bl = 0; bl < 2; bl++) {
                    mma16816(o[bl][2 * dg],     PAh[bl][kt], Bvh);
                    mma16816(o[bl][2 * dg],     PAh[bl][kt], Bvl);
                    mma16816(o[bl][2 * dg],     PAl[bl][kt], Bvh);
                    mma16816(o[bl][2 * dg + 1], PAh[bl][kt], Bvh + 2);
                    mma16816(o[bl][2 * dg + 1], PAh[bl][kt], Bvl + 2);
                    mma16816(o[bl][2 * dg + 1], PAl[bl][kt], Bvh + 2);
                }
            }
        }

        __syncthreads();
        if (c + 2 < NTILES) pf(c + 2, c & 1);
        CP_COMMIT();
    }

    // ---- epilogue: reduce lsum across quad lanes, normalize, split ----
#pragma unroll
    for (int bl = 0; bl < 2; bl++) {
#pragma unroll
        for (int r = 0; r < 2; r++) {
            lsum[bl][r] += __shfl_xor_sync(0xffffffffu, lsum[bl][r], 1);
            lsum[bl][r] += __shfl_xor_sync(0xffffffffu, lsum[bl][r], 2);
        }
        float inv0 = 1.0f / lsum[bl][0];
        float inv1 = 1.0f / lsum[bl][1];
        const int r0 = b * LL + q0 + wid * 32 + bl * 16 + (lid >> 2);
#pragma unroll
        for (int nt = 0; nt < 8; nt++) {
            int cc = h * 64 + nt * 8 + ((lid & 3) << 1);
            float v0 = o[bl][nt][0] * inv0, v1 = o[bl][nt][1] * inv0;
            float v2 = o[bl][nt][2] * inv1, v3 = o[bl][nt][3] * inv1;
            float h0 = bfhi(v0), h1 = bfhi(v1), h2 = bfhi(v2), h3 = bfhi(v3);
            size_t oa = (size_t)r0 * 1024 + cc;
            size_t ob = (size_t)(r0 + 8) * 1024 + cc;
            *(uint32_t*)&cthi[oa] = packbf(h0, h1);
            *(uint32_t*)&ctlo[oa] = packbf(v0 - h0, v1 - h1);
            *(uint32_t*)&cthi[ob] = packbf(h2, h3);
            *(uint32_t*)&ctlo[ob] = packbf(v2 - h2, v3 - h3);
        }
    }
}

// ---------------------------------------------------------------------------
// kernel_launch: 0 prep  1 gemm_qkv  2 attn_mma  3 gemm_o
// ---------------------------------------------------------------------------
extern "C" void kernel_launch(void* const* d_in, const int* in_sizes, int n_in,
                              void* d_out, int out_size) {
    const float* x  = (const float*)d_in[0];
    const float* Wq = (const float*)d_in[1];
    const float* Wk = (const float*)d_in[2];
    const float* Wv = (const float*)d_in[3];
    const float* Wo = (const float*)d_in[4];
    float* out = (float*)d_out;

    __nv_bfloat16 *xhi, *xlo, *cthi, *ctlo;
    __nv_bfloat16 *wqh, *wql, *wkvh, *wkvl, *woh, *wol;
    __nv_bfloat16 *aqh, *aql, *akh, *akl, *avh, *avl;
    float *ct, *st;
    cudaGetSymbolAddress((void**)&xhi,  g_xhi);
    cudaGetSymbolAddress((void**)&xlo,  g_xlo);
    cudaGetSymbolAddress((void**)&cthi, g_ctxhi);
    cudaGetSymbolAddress((void**)&ctlo, g_ctxlo);
    cudaGetSymbolAddress((void**)&wqh,  g_wqt_h);
    cudaGetSymbolAddress((void**)&wql,  g_wqt_l);
    cudaGetSymbolAddress((void**)&wkvh, g_wkvt_h);
    cudaGetSymbolAddress((void**)&wkvl, g_wkvt_l);
    cudaGetSymbolAddress((void**)&woh,  g_wot_h);
    cudaGetSymbolAddress((void**)&wol,  g_wot_l);
    cudaGetSymbolAddress((void**)&aqh,  g_qh);
    cudaGetSymbolAddress((void**)&aql,  g_ql);
    cudaGetSymbolAddress((void**)&akh,  g_kh);
    cudaGetSymbolAddress((void**)&akl,  g_kl);
    cudaGetSymbolAddress((void**)&avh,  g_vh);
    cudaGetSymbolAddress((void**)&avl,  g_vl);
    cudaGetSymbolAddress((void**)&ct,   g_cos);
    cudaGetSymbolAddress((void**)&st,   g_sin);

    const int smem_gemm = 2 * STG_BYTES;
    cudaFuncSetAttribute(gemm_qkv, cudaFuncAttributeMaxDynamicSharedMemorySize,
                         smem_gemm);
    cudaFuncSetAttribute(gemm_o, cudaFuncAttributeMaxDynamicSharedMemorySize,
                         smem_gemm);
    cudaFuncSetAttribute(attn_mma, cudaFuncAttributeMaxDynamicSharedMemorySize,
                         ATT_SMEM);

    dim3 blk(256);

    // 0: fused preprocessing (split + transposes + rope tables)
    prep<<<PREP_TOTAL, blk>>>(x, Wq, Wk, Wv, Wo, xhi, xlo,
                              wqh, wql, wkvh, wkvl, woh, wol, ct, st);

    // 1: QKV projection with fused RoPE + bf16 split epilogue
    gemm_qkv<<<dim3(12, BL / 128), blk, smem_gemm>>>(
        xhi, xlo, wqh, wql, wkvh, wkvl, aqh, aql, akh, akl, avh, avl, ct, st);

    // 2: tensor-core attention (analytic-max softmax)
    attn_mma<<<dim3(LL / 256, HH, BB), blk, ATT_SMEM>>>(
        aqh, aql, akh, akl, avh, avl, cthi, ctlo);

    // 3: output projection
    gemm_o<<<dim3(8, BL / 128), blk, smem_gemm>>>(
        cthi, ctlo, woh, wol, out, DD, DD);
}